// round 1
// baseline (speedup 1.0000x reference)
#include <cuda_runtime.h>
#include <cuda_bf16.h>

#define B_ 32
#define N_ 4096
#define D_ 256
#define S_ 11
#define H_ 256
#define M_ 512

// ---------------- scratch (static device globals; no allocs) ----------------
__device__ float g_mu[B_*N_];
__device__ float g_rstd[B_*N_];
__device__ float g_kf[(size_t)B_*N_*H_];
__device__ float g_vf[(size_t)B_*N_*H_];
__device__ float g_attn[(size_t)B_*N_*S_];
__device__ float g_colsum[B_*S_];
__device__ float g_q[B_*S_*H_];
__device__ float g_lntmp[B_*S_*H_];
__device__ float g_updates[B_*S_*H_];
__device__ float g_gx[B_*S_*3*H_];
__device__ float g_hid[B_*S_*M_];

// ---------------- helpers ----------------
__device__ __forceinline__ unsigned long long pk2(float x) {
    unsigned long long r;
    asm("mov.b64 %0, {%1, %1};" : "=l"(r) : "f"(x));
    return r;
}
__device__ __forceinline__ void fma2(unsigned long long& d, unsigned long long a, unsigned long long b) {
    asm("fma.rn.f32x2 %0, %1, %2, %0;" : "+l"(d) : "l"(a), "l"(b));
}

__device__ __forceinline__ void block_reduce2(float& s, float& q) {
    #pragma unroll
    for (int off = 16; off; off >>= 1) {
        s += __shfl_xor_sync(0xffffffffu, s, off);
        q += __shfl_xor_sync(0xffffffffu, q, off);
    }
    __shared__ float ss[8], sq[8];
    int w = threadIdx.x >> 5, l = threadIdx.x & 31;
    if (l == 0) { ss[w] = s; sq[w] = q; }
    __syncthreads();
    s = 0.f; q = 0.f;
    #pragma unroll
    for (int i = 0; i < 8; i++) { s += ss[i]; q += sq[i]; }
}

// ---------------- 1) per-row LN stats for inputs ----------------
__global__ void __launch_bounds__(256) k_rowstats(const float* __restrict__ x) {
    int row = blockIdx.x;
    int tid = threadIdx.x;
    float v = x[(size_t)row * 256 + tid];
    float s = v, q = v * v;
    block_reduce2(s, q);
    if (tid == 0) {
        float mu = s * (1.f / 256.f);
        float var = q * (1.f / 256.f) - mu * mu;
        g_mu[row] = mu;
        g_rstd[row] = rsqrtf(var + 1e-5f);
    }
}

// ---------------- 2) fused LN + dual GEMM: kf = LN(x)@Wk, vf = LN(x)@Wv ----------------
// C[131072,512] tiles of 128x128, BK=16, 256 threads, thread tile 8x8 via f32x2.
__global__ void __launch_bounds__(256) k_gemm_kv(
    const float* __restrict__ x, const float* __restrict__ wk, const float* __restrict__ wv,
    const float* __restrict__ lg, const float* __restrict__ lo)
{
    __shared__ unsigned long long As2[16][128];  // A duplicated-pair (a,a)
    __shared__ float Bs[16][128];
    __shared__ float sg[256], so[256], smu[128], srstd[128];

    int tid = threadIdx.x;
    int bxc = blockIdx.x;          // 0..3 column tile (0,1 -> Wk; 2,3 -> Wv)
    int rowbase = blockIdx.y * 128;

    const float* W = (bxc < 2) ? wk : wv;
    int jw = (bxc & 1) * 128;

    sg[tid] = lg[tid];
    so[tid] = lo[tid];
    if (tid < 128) {
        smu[tid] = g_mu[rowbase + tid];
        srstd[tid] = g_rstd[rowbase + tid];
    }
    __syncthreads();

    unsigned long long acc[8][4];
    #pragma unroll
    for (int i = 0; i < 8; i++)
        #pragma unroll
        for (int j = 0; j < 4; j++) acc[i][j] = 0ull;

    int ty = tid >> 4, tx = tid & 15;

    for (int kt = 0; kt < 16; kt++) {
        int kb = kt * 16;
        // load A tile 128x16 (LN applied), store as duplicated pairs transposed
        #pragma unroll
        for (int i = 0; i < 2; i++) {
            int idx4 = tid + i * 256;
            int row = idx4 >> 2;
            int kq = (idx4 & 3) * 4;
            float4 xv = *(const float4*)&x[(size_t)(rowbase + row) * 256 + kb + kq];
            float m = smu[row], rs = srstd[row];
            float v0 = (xv.x - m) * rs * sg[kb + kq + 0] + so[kb + kq + 0];
            float v1 = (xv.y - m) * rs * sg[kb + kq + 1] + so[kb + kq + 1];
            float v2 = (xv.z - m) * rs * sg[kb + kq + 2] + so[kb + kq + 2];
            float v3 = (xv.w - m) * rs * sg[kb + kq + 3] + so[kb + kq + 3];
            As2[kq + 0][row] = pk2(v0);
            As2[kq + 1][row] = pk2(v1);
            As2[kq + 2][row] = pk2(v2);
            As2[kq + 3][row] = pk2(v3);
        }
        // load B tile 16x128
        #pragma unroll
        for (int i = 0; i < 2; i++) {
            int idx4 = tid + i * 256;
            int k = idx4 >> 5;
            int c = (idx4 & 31) * 4;
            *(float4*)&Bs[k][c] = *(const float4*)&W[(size_t)(kb + k) * 256 + jw + c];
        }
        __syncthreads();

        #pragma unroll
        for (int kk = 0; kk < 16; kk++) {
            unsigned long long a2[8], b2[4];
            #pragma unroll
            for (int i = 0; i < 8; i++) a2[i] = As2[kk][ty * 8 + i];
            const unsigned long long* bp = (const unsigned long long*)&Bs[kk][tx * 8];
            #pragma unroll
            for (int j = 0; j < 4; j++) b2[j] = bp[j];
            #pragma unroll
            for (int i = 0; i < 8; i++)
                #pragma unroll
                for (int j = 0; j < 4; j++) fma2(acc[i][j], a2[i], b2[j]);
        }
        __syncthreads();
    }

    float* outp = (bxc < 2) ? g_kf : g_vf;
    #pragma unroll
    for (int i = 0; i < 8; i++) {
        unsigned long long* o =
            (unsigned long long*)&outp[(size_t)(rowbase + ty * 8 + i) * 256 + jw + tx * 8];
        #pragma unroll
        for (int j = 0; j < 4; j++) o[j] = acc[i][j];
    }
}

// ---------------- 3) slots init: mu + exp(log_sigma)*noise -> d_out ----------------
__global__ void __launch_bounds__(256) k_init(const float* __restrict__ noise,
                                              const float* __restrict__ mu,
                                              const float* __restrict__ ls,
                                              float* __restrict__ slots)
{
    int i = blockIdx.x * 256 + threadIdx.x;   // 0..90111
    int h = i & 255;
    slots[i] = mu[h] + expf(ls[h]) * noise[i];
}

// ---------------- 4) generic 256-wide row LN: g_lntmp = LN(src) ----------------
__global__ void __launch_bounds__(256) k_ln256(const float* __restrict__ src,
                                               const float* __restrict__ g,
                                               const float* __restrict__ o)
{
    int row = blockIdx.x;
    int tid = threadIdx.x;
    float v = src[(size_t)row * 256 + tid];
    float s = v, q = v * v;
    block_reduce2(s, q);
    float mu = s * (1.f / 256.f);
    float var = q * (1.f / 256.f) - mu * mu;
    float rs = rsqrtf(var + 1e-5f);
    g_lntmp[(size_t)row * 256 + tid] = (v - mu) * rs * g[tid] + o[tid];
}

// ---------------- 5) small batched GEMM over the 352 slot rows ----------------
// mode 0: q    = g_lntmp   @ Wq * scale            (K=256,J=256)
// mode 1: gx   = g_updates @ gru_wi                (K=256,J=768)
// mode 2: hid  = relu(g_lntmp @ w1 + b1)           (K=256,J=512)
// mode 3: slots += g_hid @ w2 + b2                 (K=512,J=256)
__global__ void __launch_bounds__(256) k_sgemm(int mode, const float* __restrict__ W,
                                               const float* __restrict__ bias,
                                               float* __restrict__ slots, float scale)
{
    __shared__ float ins[512 * 12];
    int b = blockIdx.x;
    int jt = blockIdx.y;
    int tid = threadIdx.x;
    int K = (mode == 3) ? 512 : 256;
    int J = (mode == 0) ? 256 : (mode == 1) ? 768 : (mode == 2) ? 512 : 256;
    const float* in = (mode == 1) ? g_updates : (mode == 3) ? g_hid : g_lntmp;
    float* out = (mode == 0) ? g_q : (mode == 1) ? g_gx : (mode == 2) ? g_hid : slots;

    const float* ip = &in[(size_t)b * 11 * K];
    for (int i = tid; i < 11 * K; i += 256) {
        int s = i / K;
        int k = i - s * K;
        ins[k * 12 + s] = ip[i];
    }
    __syncthreads();

    int j = jt * 256 + tid;
    float acc[11];
    #pragma unroll
    for (int s = 0; s < 11; s++) acc[s] = 0.f;

    const float* wp = &W[j];
    #pragma unroll 2
    for (int k = 0; k < K; k++) {
        float w = wp[(size_t)k * J];
        const float4* s4 = (const float4*)&ins[k * 12];
        float4 A0 = s4[0], A1 = s4[1], A2 = s4[2];
        acc[0] += A0.x * w; acc[1] += A0.y * w; acc[2] += A0.z * w; acc[3] += A0.w * w;
        acc[4] += A1.x * w; acc[5] += A1.y * w; acc[6] += A1.z * w; acc[7] += A1.w * w;
        acc[8] += A2.x * w; acc[9] += A2.y * w; acc[10] += A2.z * w;
    }

    float bb = bias ? bias[j] : 0.f;
    #pragma unroll
    for (int s = 0; s < 11; s++) {
        float v = acc[s] * scale + bb;
        if (mode == 2) v = fmaxf(v, 0.f);
        size_t oi = ((size_t)b * 11 + s) * J + j;
        if (mode == 3) out[oi] = slots[oi] + v;
        else out[oi] = v;
    }
}

// ---------------- 6) zero accumulators for the iteration ----------------
__global__ void __launch_bounds__(256) k_zero() {
    int i = blockIdx.x * 256 + threadIdx.x;   // 352*256 = 90112 threads
    if (i < B_ * S_) g_colsum[i] = 0.f;
    g_updates[i] = 0.f;
}

// ---------------- 7) attention logits + softmax + eps + column-sum ----------------
__global__ void __launch_bounds__(256) k_attn() {
    __shared__ float qs[11][256];
    __shared__ float scs[11];
    int b = blockIdx.x;
    int chunk = blockIdx.y;    // 128 chunks of 32 rows
    int tid = threadIdx.x;

    for (int i = tid; i < 11 * 256; i += 256) qs[i >> 8][i & 255] = g_q[b * 11 * 256 + i];
    if (tid < 11) scs[tid] = 0.f;
    __syncthreads();

    int warp = tid >> 5, lane = tid & 31;
    #pragma unroll
    for (int rr = 0; rr < 4; rr++) {
        int n = chunk * 32 + warp * 4 + rr;
        const float* kfp = &g_kf[((size_t)b * 4096 + n) * 256];
        float acc[11];
        #pragma unroll
        for (int s = 0; s < 11; s++) acc[s] = 0.f;
        #pragma unroll
        for (int i = 0; i < 8; i++) {
            float xv = kfp[i * 32 + lane];
            #pragma unroll
            for (int s = 0; s < 11; s++) acc[s] += xv * qs[s][i * 32 + lane];
        }
        #pragma unroll
        for (int off = 16; off; off >>= 1) {
            #pragma unroll
            for (int s = 0; s < 11; s++) acc[s] += __shfl_xor_sync(0xffffffffu, acc[s], off);
        }
        if (lane == 0) {
            float m = acc[0];
            #pragma unroll
            for (int s = 1; s < 11; s++) m = fmaxf(m, acc[s]);
            float e[11], sum = 0.f;
            #pragma unroll
            for (int s = 0; s < 11; s++) { e[s] = expf(acc[s] - m); sum += e[s]; }
            float inv = 1.f / sum;
            float* ap = &g_attn[((size_t)b * 4096 + n) * 11];
            #pragma unroll
            for (int s = 0; s < 11; s++) {
                float p = e[s] * inv + 1e-8f;
                ap[s] = p;
                atomicAdd(&scs[s], p);
            }
        }
    }
    __syncthreads();
    if (tid < 11) atomicAdd(&g_colsum[b * 11 + tid], scs[tid]);
}

// ---------------- 8) updates[b,s,h] = sum_n (attn/colsum) * vf ----------------
__global__ void __launch_bounds__(256) k_updates() {
    __shared__ float sa[256 * 12];
    __shared__ float sinv[11];
    int b = blockIdx.x;
    int chunk = blockIdx.y;    // 16 chunks of 256 rows
    int tid = threadIdx.x;
    if (tid < 11) sinv[tid] = 1.f / g_colsum[b * 11 + tid];
    int nb = chunk * 256;
    const float* ap = &g_attn[((size_t)b * 4096 + nb) * 11];
    for (int i = tid; i < 256 * 11; i += 256) {
        int n = i / 11;
        int s = i - n * 11;
        sa[n * 12 + s] = ap[i];
    }
    __syncthreads();

    float acc[11];
    #pragma unroll
    for (int s = 0; s < 11; s++) acc[s] = 0.f;
    const float* vp = &g_vf[((size_t)b * 4096 + nb) * 256 + tid];
    #pragma unroll 2
    for (int n = 0; n < 256; n++) {
        float v = vp[(size_t)n * 256];
        const float4* s4 = (const float4*)&sa[n * 12];
        float4 A0 = s4[0], A1 = s4[1], A2 = s4[2];
        acc[0] += A0.x * v; acc[1] += A0.y * v; acc[2] += A0.z * v; acc[3] += A0.w * v;
        acc[4] += A1.x * v; acc[5] += A1.y * v; acc[6] += A1.z * v; acc[7] += A1.w * v;
        acc[8] += A2.x * v; acc[9] += A2.y * v; acc[10] += A2.z * v;
    }
    float* up = &g_updates[(b * 11) * 256 + tid];
    #pragma unroll
    for (int s = 0; s < 11; s++) atomicAdd(&up[s * 256], acc[s] * sinv[s]);
}

// ---------------- 9) GRU scan over 11 steps (one CTA per batch) ----------------
__global__ void __launch_bounds__(256) k_gru(const float* __restrict__ wh,
                                             const float* __restrict__ gb,
                                             float* __restrict__ slots)
{
    __shared__ float hs[256], rh[256];
    int b = blockIdx.x;
    int tid = threadIdx.x;
    hs[tid] = 0.f;
    float bz = gb[tid], br = gb[256 + tid], ba = gb[512 + tid];
    __syncthreads();

    for (int s = 0; s < 11; s++) {
        const float* gx = &g_gx[((size_t)b * 11 + s) * 768];
        float az = gx[tid] + bz;
        float ar = gx[256 + tid] + br;
        const float* wz = wh + tid;
        const float* wr = wh + 256 + tid;
        #pragma unroll 8
        for (int k = 0; k < 256; k++) {
            float h = hs[k];
            az = fmaf(h, wz[(size_t)k * 768], az);
            ar = fmaf(h, wr[(size_t)k * 768], ar);
        }
        float z = 1.f / (1.f + expf(-az));
        float r = 1.f / (1.f + expf(-ar));
        float hold = hs[tid];
        rh[tid] = r * hold;
        __syncthreads();                        // rh complete; all done reading hs
        float aa = gx[512 + tid] + ba;
        const float* wa = wh + 512 + tid;
        #pragma unroll 8
        for (int k = 0; k < 256; k++) aa = fmaf(rh[k], wa[(size_t)k * 768], aa);
        float a = tanhf(aa);
        float hn = (1.f - z) * hold + z * a;
        slots[((size_t)b * 11 + s) * 256 + tid] = hn;
        hs[tid] = hn;
        __syncthreads();                        // hs consistent for next step
    }
}

// ---------------- host launch ----------------
extern "C" void kernel_launch(void* const* d_in, const int* in_sizes, int n_in,
                              void* d_out, int out_size)
{
    const float* inputs          = (const float*)d_in[0];
    const float* slot_noise      = (const float*)d_in[1];
    const float* ln_in_scale     = (const float*)d_in[2];
    const float* ln_in_offset    = (const float*)d_in[3];
    const float* ln_slots_scale  = (const float*)d_in[4];
    const float* ln_slots_offset = (const float*)d_in[5];
    const float* ln_mlp_scale    = (const float*)d_in[6];
    const float* ln_mlp_offset   = (const float*)d_in[7];
    const float* slots_mu        = (const float*)d_in[8];
    const float* slots_log_sigma = (const float*)d_in[9];
    const float* Wq              = (const float*)d_in[10];
    const float* Wk              = (const float*)d_in[11];
    const float* Wv              = (const float*)d_in[12];
    const float* gru_wi          = (const float*)d_in[13];
    const float* gru_wh          = (const float*)d_in[14];
    const float* gru_b           = (const float*)d_in[15];
    const float* mlp_w1          = (const float*)d_in[16];
    const float* mlp_b1          = (const float*)d_in[17];
    const float* mlp_w2          = (const float*)d_in[18];
    const float* mlp_b2          = (const float*)d_in[19];
    float* slots = (float*)d_out;

    (void)in_sizes; (void)n_in; (void)out_size;

    k_rowstats<<<B_ * N_, 256>>>(inputs);
    k_gemm_kv<<<dim3(4, (B_ * N_) / 128), 256>>>(inputs, Wk, Wv, ln_in_scale, ln_in_offset);
    k_init<<<352, 256>>>(slot_noise, slots_mu, slots_log_sigma, slots);

    for (int it = 0; it < 3; it++) {
        k_ln256<<<352, 256>>>(slots, ln_slots_scale, ln_slots_offset);
        k_sgemm<<<dim3(32, 1), 256>>>(0, Wq, nullptr, slots, 0.0625f);
        k_zero<<<352, 256>>>();
        k_attn<<<dim3(32, 128), 256>>>();
        k_updates<<<dim3(32, 16), 256>>>();
        k_sgemm<<<dim3(32, 3), 256>>>(1, gru_wi, nullptr, slots, 1.0f);
        k_gru<<<32, 256>>>(gru_wh, gru_b, slots);
        k_ln256<<<352, 256>>>(slots, ln_mlp_scale, ln_mlp_offset);
        k_sgemm<<<dim3(32, 2), 256>>>(2, mlp_w1, mlp_b1, slots, 1.0f);
        k_sgemm<<<dim3(32, 1), 256>>>(3, mlp_w2, mlp_b2, slots, 1.0f);
    }
}

// round 3
// speedup vs baseline: 1.2546x; 1.2546x over previous
#include <cuda_runtime.h>
#include <cuda_bf16.h>
#include <stdint.h>

#define B_ 32
#define N_ 4096
#define D_ 256
#define S_ 11
#define H_ 256
#define M_ 512

// ---------------- scratch (static device globals; no allocs) ----------------
__device__ __nv_bfloat16 g_ahi[(size_t)B_*N_*D_];
__device__ __nv_bfloat16 g_alo[(size_t)B_*N_*D_];
__device__ __nv_bfloat16 g_wthi[512*256];
__device__ __nv_bfloat16 g_wtlo[512*256];
__device__ float g_kf[(size_t)B_*N_*H_];
__device__ float g_vf[(size_t)B_*N_*H_];
__device__ float g_attn[(size_t)B_*N_*S_];
__device__ float g_colsum[B_*S_];
__device__ float g_q[B_*S_*H_];
__device__ float g_lntmp[B_*S_*H_];
__device__ float g_updates[B_*S_*H_];
__device__ float g_gx[B_*S_*3*H_];
__device__ float g_hid[B_*S_*M_];

// ---------------- helpers ----------------
__device__ __forceinline__ uint32_t smem_u32(const void* p) {
    uint32_t a;
    asm("{ .reg .u64 t; cvta.to.shared.u64 t, %1; cvt.u32.u64 %0, t; }" : "=r"(a) : "l"(p));
    return a;
}
__device__ __forceinline__ void ldsm_x4(uint32_t& r0, uint32_t& r1, uint32_t& r2, uint32_t& r3,
                                        uint32_t addr) {
    asm volatile("ldmatrix.sync.aligned.m8n8.x4.shared.b16 {%0,%1,%2,%3}, [%4];"
                 : "=r"(r0), "=r"(r1), "=r"(r2), "=r"(r3) : "r"(addr));
}
__device__ __forceinline__ void mma16816(float* d, const uint32_t* a, const uint32_t* b) {
    asm volatile("mma.sync.aligned.m16n8k16.row.col.f32.bf16.bf16.f32 "
                 "{%0,%1,%2,%3}, {%4,%5,%6,%7}, {%8,%9}, {%0,%1,%2,%3};"
                 : "+f"(d[0]), "+f"(d[1]), "+f"(d[2]), "+f"(d[3])
                 : "r"(a[0]), "r"(a[1]), "r"(a[2]), "r"(a[3]), "r"(b[0]), "r"(b[1]));
}

__device__ __forceinline__ void block_reduce2(float& s, float& q) {
    #pragma unroll
    for (int off = 16; off; off >>= 1) {
        s += __shfl_xor_sync(0xffffffffu, s, off);
        q += __shfl_xor_sync(0xffffffffu, q, off);
    }
    __shared__ float ss[8], sq[8];
    int w = threadIdx.x >> 5, l = threadIdx.x & 31;
    if (l == 0) { ss[w] = s; sq[w] = q; }
    __syncthreads();
    s = 0.f; q = 0.f;
    #pragma unroll
    for (int i = 0; i < 8; i++) { s += ss[i]; q += sq[i]; }
}

// ---------------- 1) fused LN-stats + LN + bf16 hi/lo split of inputs ----------------
__global__ void __launch_bounds__(256) k_prep(const float* __restrict__ x,
                                              const float* __restrict__ g,
                                              const float* __restrict__ o)
{
    int wid = threadIdx.x >> 5, lane = threadIdx.x & 31;
    int row = blockIdx.x * 8 + wid;
    const float4* xp = (const float4*)&x[(size_t)row * 256 + lane * 8];
    float4 a = xp[0], b = xp[1];
    float s = a.x + a.y + a.z + a.w + b.x + b.y + b.z + b.w;
    float q = a.x*a.x + a.y*a.y + a.z*a.z + a.w*a.w
            + b.x*b.x + b.y*b.y + b.z*b.z + b.w*b.w;
    #pragma unroll
    for (int off = 16; off; off >>= 1) {
        s += __shfl_xor_sync(0xffffffffu, s, off);
        q += __shfl_xor_sync(0xffffffffu, q, off);
    }
    float mu = s * (1.f / 256.f);
    float var = q * (1.f / 256.f) - mu * mu;
    float rs = rsqrtf(var + 1e-5f);

    const float4* gp = (const float4*)&g[lane * 8];
    const float4* op = (const float4*)&o[lane * 8];
    float4 g0 = gp[0], g1 = gp[1], o0 = op[0], o1 = op[1];

    float v[8];
    v[0] = (a.x - mu) * rs * g0.x + o0.x;
    v[1] = (a.y - mu) * rs * g0.y + o0.y;
    v[2] = (a.z - mu) * rs * g0.z + o0.z;
    v[3] = (a.w - mu) * rs * g0.w + o0.w;
    v[4] = (b.x - mu) * rs * g1.x + o1.x;
    v[5] = (b.y - mu) * rs * g1.y + o1.y;
    v[6] = (b.z - mu) * rs * g1.z + o1.z;
    v[7] = (b.w - mu) * rs * g1.w + o1.w;

    float hf[8], lf[8];
    #pragma unroll
    for (int i = 0; i < 8; i++) {
        __nv_bfloat16 h = __float2bfloat16_rn(v[i]);
        hf[i] = __bfloat162float(h);
        lf[i] = v[i] - hf[i];
    }
    __nv_bfloat162 h01 = __floats2bfloat162_rn(hf[0], hf[1]);
    __nv_bfloat162 h23 = __floats2bfloat162_rn(hf[2], hf[3]);
    __nv_bfloat162 h45 = __floats2bfloat162_rn(hf[4], hf[5]);
    __nv_bfloat162 h67 = __floats2bfloat162_rn(hf[6], hf[7]);
    __nv_bfloat162 l01 = __floats2bfloat162_rn(lf[0], lf[1]);
    __nv_bfloat162 l23 = __floats2bfloat162_rn(lf[2], lf[3]);
    __nv_bfloat162 l45 = __floats2bfloat162_rn(lf[4], lf[5]);
    __nv_bfloat162 l67 = __floats2bfloat162_rn(lf[6], lf[7]);
    uint4 uh, ul;
    uh.x = *(uint32_t*)&h01; uh.y = *(uint32_t*)&h23; uh.z = *(uint32_t*)&h45; uh.w = *(uint32_t*)&h67;
    ul.x = *(uint32_t*)&l01; ul.y = *(uint32_t*)&l23; ul.z = *(uint32_t*)&l45; ul.w = *(uint32_t*)&l67;
    *(uint4*)&g_ahi[(size_t)row * 256 + lane * 8] = uh;
    *(uint4*)&g_alo[(size_t)row * 256 + lane * 8] = ul;
}

// ---------------- 2) weight transpose + bf16 split: g_wt[j][k] = W[k][j] ----------------
__global__ void __launch_bounds__(256) k_wprep(const float* __restrict__ wk,
                                               const float* __restrict__ wv)
{
    int idx = blockIdx.x * 256 + threadIdx.x;   // 0..131071
    int j = idx >> 8;
    int k = idx & 255;
    float w = (j < 256) ? wk[k * 256 + j] : wv[k * 256 + (j - 256)];
    __nv_bfloat16 h = __float2bfloat16_rn(w);
    float hf = __bfloat162float(h);
    g_wthi[idx] = h;
    g_wtlo[idx] = __float2bfloat16_rn(w - hf);
}

// ---------------- 3) mma.sync split-bf16 GEMM: kf/vf = LN(x) @ {Wk,Wv} ----------------
// CTA tile M=128, N=128, K chunks of 64. Smem 64KB swizzled.
// blockIdx.x: bit1 = half (0->kf via Wk, 1->vf via Wv), bit0 = n-tile (0/1 -> cols 0-127/128-255)
#define SM_AH 0
#define SM_AL 16384
#define SM_BH 32768
#define SM_BL 49152
#define SMEM_SZ 65536

__global__ void __launch_bounds__(256, 1) k_mma_kv()
{
    extern __shared__ __align__(1024) uint8_t smem[];
    uint32_t sbase = smem_u32(smem);
    int tid = threadIdx.x;
    int lane = tid & 31;
    int warp = tid >> 5;
    int wm = warp & 3;          // 4 M-blocks of 32
    int wn = warp >> 2;         // 2 N-blocks of 64

    int half = blockIdx.x >> 1;
    int ntile = blockIdx.x & 1;
    int rowbase = blockIdx.y * 128;
    size_t jb = ((size_t)half * 256 + ntile * 128) * 256;   // row base into g_wt

    float acc[2][8][4];
    #pragma unroll
    for (int mf = 0; mf < 2; mf++)
        #pragma unroll
        for (int nf = 0; nf < 8; nf++)
            #pragma unroll
            for (int r = 0; r < 4; r++) acc[mf][nf][r] = 0.f;

    // ldmatrix per-thread source row/col within a 16x16 block
    uint32_t lrow = ((lane >> 3) & 1) * 8 + (lane & 7);
    uint32_t lcol = ((lane >> 4) & 1) * 16;   // byte offset

    for (int ch = 0; ch < 4; ch++) {
        int kb = ch * 64;
        // fill A tiles (128 rows x 64 bf16 = 128B/row) and B tiles (128 n-rows x 64 bf16)
        #pragma unroll
        for (int i = 0; i < 4; i++) {
            int idx = tid + i * 256;          // 0..1023
            int row = idx >> 3, c8 = idx & 7;
            uint32_t bo = row * 128 + c8 * 16;
            uint32_t sw = bo ^ ((bo >> 3) & 0x70);
            size_t srcA = (size_t)(rowbase + row) * 256 + kb + c8 * 8;
            size_t srcB = jb + (size_t)row * 256 + kb + c8 * 8;
            *(uint4*)(smem + SM_AH + sw) = *(const uint4*)&g_ahi[srcA];
            *(uint4*)(smem + SM_AL + sw) = *(const uint4*)&g_alo[srcA];
            *(uint4*)(smem + SM_BH + sw) = *(const uint4*)&g_wthi[srcB];
            *(uint4*)(smem + SM_BL + sw) = *(const uint4*)&g_wtlo[srcB];
        }
        __syncthreads();

        #pragma unroll
        for (int ks = 0; ks < 4; ks++) {
            uint32_t cb = ks * 32 + lcol;
            // A fragments
            uint32_t ah[2][4], al[2][4];
            #pragma unroll
            for (int mf = 0; mf < 2; mf++) {
                uint32_t r = wm * 32 + mf * 16 + lrow;
                uint32_t bo = r * 128 + cb;
                uint32_t sw = bo ^ ((bo >> 3) & 0x70);
                ldsm_x4(ah[mf][0], ah[mf][1], ah[mf][2], ah[mf][3], sbase + SM_AH + sw);
                ldsm_x4(al[mf][0], al[mf][1], al[mf][2], al[mf][3], sbase + SM_AL + sw);
            }
            // B fragments (8 n-frags as 4 groups of n16)
            uint32_t bh[8][2], bl[8][2];
            #pragma unroll
            for (int g = 0; g < 4; g++) {
                uint32_t r = wn * 64 + g * 16 + lrow;
                uint32_t bo = r * 128 + cb;
                uint32_t sw = bo ^ ((bo >> 3) & 0x70);
                uint32_t t0, t1, t2, t3;
                ldsm_x4(t0, t1, t2, t3, sbase + SM_BH + sw);
                bh[g * 2][0] = t0; bh[g * 2 + 1][0] = t1;
                bh[g * 2][1] = t2; bh[g * 2 + 1][1] = t3;
                ldsm_x4(t0, t1, t2, t3, sbase + SM_BL + sw);
                bl[g * 2][0] = t0; bl[g * 2 + 1][0] = t1;
                bl[g * 2][1] = t2; bl[g * 2 + 1][1] = t3;
            }
            // 3-product split-bf16 MMA
            #pragma unroll
            for (int mf = 0; mf < 2; mf++)
                #pragma unroll
                for (int nf = 0; nf < 8; nf++) {
                    mma16816(acc[mf][nf], ah[mf], bh[nf]);
                    mma16816(acc[mf][nf], ah[mf], bl[nf]);
                    mma16816(acc[mf][nf], al[mf], bh[nf]);
                }
        }
        __syncthreads();
    }

    // epilogue
    float* outp = (half == 0) ? g_kf : g_vf;
    int r0 = rowbase + wm * 32 + (lane >> 2);
    int c0 = ntile * 128 + wn * 64 + (lane & 3) * 2;
    #pragma unroll
    for (int mf = 0; mf < 2; mf++)
        #pragma unroll
        for (int nf = 0; nf < 8; nf++) {
            float* d = acc[mf][nf];
            size_t base = (size_t)(r0 + mf * 16) * 256 + c0 + nf * 8;
            *(float2*)&outp[base] = make_float2(d[0], d[1]);
            *(float2*)&outp[base + 8 * 256] = make_float2(d[2], d[3]);
        }
}

// ---------------- 4) slots init ----------------
__global__ void __launch_bounds__(256) k_init(const float* __restrict__ noise,
                                              const float* __restrict__ mu,
                                              const float* __restrict__ ls,
                                              float* __restrict__ slots)
{
    int i = blockIdx.x * 256 + threadIdx.x;
    int h = i & 255;
    slots[i] = mu[h] + expf(ls[h]) * noise[i];
}

// ---------------- 5) generic 256-wide row LN ----------------
__global__ void __launch_bounds__(256) k_ln256(const float* __restrict__ src,
                                               const float* __restrict__ g,
                                               const float* __restrict__ o)
{
    int row = blockIdx.x;
    int tid = threadIdx.x;
    float v = src[(size_t)row * 256 + tid];
    float s = v, q = v * v;
    block_reduce2(s, q);
    float mu = s * (1.f / 256.f);
    float var = q * (1.f / 256.f) - mu * mu;
    float rs = rsqrtf(var + 1e-5f);
    g_lntmp[(size_t)row * 256 + tid] = (v - mu) * rs * g[tid] + o[tid];
}

// ---------------- 6) small batched GEMM over the 352 slot rows ----------------
__global__ void __launch_bounds__(256) k_sgemm(int mode, const float* __restrict__ W,
                                               const float* __restrict__ bias,
                                               float* __restrict__ slots, float scale)
{
    __shared__ float ins[512 * 12];
    int b = blockIdx.x;
    int jt = blockIdx.y;
    int tid = threadIdx.x;
    int K = (mode == 3) ? 512 : 256;
    int J = (mode == 0) ? 256 : (mode == 1) ? 768 : (mode == 2) ? 512 : 256;
    const float* in = (mode == 1) ? g_updates : (mode == 3) ? g_hid : g_lntmp;
    float* out = (mode == 0) ? g_q : (mode == 1) ? g_gx : (mode == 2) ? g_hid : slots;

    const float* ip = &in[(size_t)b * 11 * K];
    for (int i = tid; i < 11 * K; i += 256) {
        int s = i / K;
        int k = i - s * K;
        ins[k * 12 + s] = ip[i];
    }
    __syncthreads();

    int j = jt * 256 + tid;
    float acc[11];
    #pragma unroll
    for (int s = 0; s < 11; s++) acc[s] = 0.f;

    const float* wp = &W[j];
    #pragma unroll 2
    for (int k = 0; k < K; k++) {
        float w = wp[(size_t)k * J];
        const float4* s4 = (const float4*)&ins[k * 12];
        float4 A0 = s4[0], A1 = s4[1], A2 = s4[2];
        acc[0] += A0.x * w; acc[1] += A0.y * w; acc[2] += A0.z * w; acc[3] += A0.w * w;
        acc[4] += A1.x * w; acc[5] += A1.y * w; acc[6] += A1.z * w; acc[7] += A1.w * w;
        acc[8] += A2.x * w; acc[9] += A2.y * w; acc[10] += A2.z * w;
    }

    float bb = bias ? bias[j] : 0.f;
    #pragma unroll
    for (int s = 0; s < 11; s++) {
        float v = acc[s] * scale + bb;
        if (mode == 2) v = fmaxf(v, 0.f);
        size_t oi = ((size_t)b * 11 + s) * J + j;
        if (mode == 3) out[oi] = slots[oi] + v;
        else out[oi] = v;
    }
}

// ---------------- 7) zero accumulators ----------------
__global__ void __launch_bounds__(256) k_zero() {
    int i = blockIdx.x * 256 + threadIdx.x;
    if (i < B_ * S_) g_colsum[i] = 0.f;
    g_updates[i] = 0.f;
}

// ---------------- 8) attention logits + softmax + eps + column-sum ----------------
__global__ void __launch_bounds__(256) k_attn() {
    __shared__ float qs[11][256];
    __shared__ float scs[11];
    int b = blockIdx.x;
    int chunk = blockIdx.y;
    int tid = threadIdx.x;

    for (int i = tid; i < 11 * 256; i += 256) qs[i >> 8][i & 255] = g_q[b * 11 * 256 + i];
    if (tid < 11) scs[tid] = 0.f;
    __syncthreads();

    int warp = tid >> 5, lane = tid & 31;
    #pragma unroll
    for (int rr = 0; rr < 4; rr++) {
        int n = chunk * 32 + warp * 4 + rr;
        const float* kfp = &g_kf[((size_t)b * 4096 + n) * 256];
        float acc[11];
        #pragma unroll
        for (int s = 0; s < 11; s++) acc[s] = 0.f;
        #pragma unroll
        for (int i = 0; i < 8; i++) {
            float xv = kfp[i * 32 + lane];
            #pragma unroll
            for (int s = 0; s < 11; s++) acc[s] += xv * qs[s][i * 32 + lane];
        }
        #pragma unroll
        for (int off = 16; off; off >>= 1) {
            #pragma unroll
            for (int s = 0; s < 11; s++) acc[s] += __shfl_xor_sync(0xffffffffu, acc[s], off);
        }
        if (lane == 0) {
            float m = acc[0];
            #pragma unroll
            for (int s = 1; s < 11; s++) m = fmaxf(m, acc[s]);
            float e[11], sum = 0.f;
            #pragma unroll
            for (int s = 0; s < 11; s++) { e[s] = expf(acc[s] - m); sum += e[s]; }
            float inv = 1.f / sum;
            float* ap = &g_attn[((size_t)b * 4096 + n) * 11];
            #pragma unroll
            for (int s = 0; s < 11; s++) {
                float p = e[s] * inv + 1e-8f;
                ap[s] = p;
                atomicAdd(&scs[s], p);
            }
        }
    }
    __syncthreads();
    if (tid < 11) atomicAdd(&g_colsum[b * 11 + tid], scs[tid]);
}

// ---------------- 9) updates[b,s,h] = sum_n (attn/colsum) * vf ----------------
__global__ void __launch_bounds__(256) k_updates() {
    __shared__ float sa[256 * 12];
    __shared__ float sinv[11];
    int b = blockIdx.x;
    int chunk = blockIdx.y;
    int tid = threadIdx.x;
    if (tid < 11) sinv[tid] = 1.f / g_colsum[b * 11 + tid];
    int nb = chunk * 256;
    const float* ap = &g_attn[((size_t)b * 4096 + nb) * 11];
    for (int i = tid; i < 256 * 11; i += 256) {
        int n = i / 11;
        int s = i - n * 11;
        sa[n * 12 + s] = ap[i];
    }
    __syncthreads();

    float acc[11];
    #pragma unroll
    for (int s = 0; s < 11; s++) acc[s] = 0.f;
    const float* vp = &g_vf[((size_t)b * 4096 + nb) * 256 + tid];
    #pragma unroll 2
    for (int n = 0; n < 256; n++) {
        float v = vp[(size_t)n * 256];
        const float4* s4 = (const float4*)&sa[n * 12];
        float4 A0 = s4[0], A1 = s4[1], A2 = s4[2];
        acc[0] += A0.x * v; acc[1] += A0.y * v; acc[2] += A0.z * v; acc[3] += A0.w * v;
        acc[4] += A1.x * v; acc[5] += A1.y * v; acc[6] += A1.z * v; acc[7] += A1.w * v;
        acc[8] += A2.x * v; acc[9] += A2.y * v; acc[10] += A2.z * v;
    }
    float* up = &g_updates[(b * 11) * 256 + tid];
    #pragma unroll
    for (int s = 0; s < 11; s++) atomicAdd(&up[s * 256], acc[s] * sinv[s]);
}

// ---------------- 10) GRU scan over 11 steps (one CTA per batch) ----------------
__global__ void __launch_bounds__(256) k_gru(const float* __restrict__ wh,
                                             const float* __restrict__ gb,
                                             float* __restrict__ slots)
{
    __shared__ float hs[256], rh[256];
    int b = blockIdx.x;
    int tid = threadIdx.x;
    hs[tid] = 0.f;
    float bz = gb[tid], br = gb[256 + tid], ba = gb[512 + tid];
    __syncthreads();

    for (int s = 0; s < 11; s++) {
        const float* gx = &g_gx[((size_t)b * 11 + s) * 768];
        float az = gx[tid] + bz;
        float ar = gx[256 + tid] + br;
        const float* wz = wh + tid;
        const float* wr = wh + 256 + tid;
        #pragma unroll 8
        for (int k = 0; k < 256; k++) {
            float h = hs[k];
            az = fmaf(h, wz[(size_t)k * 768], az);
            ar = fmaf(h, wr[(size_t)k * 768], ar);
        }
        float z = 1.f / (1.f + expf(-az));
        float r = 1.f / (1.f + expf(-ar));
        float hold = hs[tid];
        rh[tid] = r * hold;
        __syncthreads();
        float aa = gx[512 + tid] + ba;
        const float* wa = wh + 512 + tid;
        #pragma unroll 8
        for (int k = 0; k < 256; k++) aa = fmaf(rh[k], wa[(size_t)k * 768], aa);
        float a = tanhf(aa);
        float hn = (1.f - z) * hold + z * a;
        slots[((size_t)b * 11 + s) * 256 + tid] = hn;
        hs[tid] = hn;
        __syncthreads();
    }
}

// ---------------- host launch ----------------
extern "C" void kernel_launch(void* const* d_in, const int* in_sizes, int n_in,
                              void* d_out, int out_size)
{
    const float* inputs          = (const float*)d_in[0];
    const float* slot_noise      = (const float*)d_in[1];
    const float* ln_in_scale     = (const float*)d_in[2];
    const float* ln_in_offset    = (const float*)d_in[3];
    const float* ln_slots_scale  = (const float*)d_in[4];
    const float* ln_slots_offset = (const float*)d_in[5];
    const float* ln_mlp_scale    = (const float*)d_in[6];
    const float* ln_mlp_offset   = (const float*)d_in[7];
    const float* slots_mu        = (const float*)d_in[8];
    const float* slots_log_sigma = (const float*)d_in[9];
    const float* Wq              = (const float*)d_in[10];
    const float* Wk              = (const float*)d_in[11];
    const float* Wv              = (const float*)d_in[12];
    const float* gru_wi          = (const float*)d_in[13];
    const float* gru_wh          = (const float*)d_in[14];
    const float* gru_b           = (const float*)d_in[15];
    const float* mlp_w1          = (const float*)d_in[16];
    const float* mlp_b1          = (const float*)d_in[17];
    const float* mlp_w2          = (const float*)d_in[18];
    const float* mlp_b2          = (const float*)d_in[19];
    float* slots = (float*)d_out;

    (void)in_sizes; (void)n_in; (void)out_size;

    cudaFuncSetAttribute(k_mma_kv, cudaFuncAttributeMaxDynamicSharedMemorySize, SMEM_SZ);

    k_prep<<<(B_ * N_) / 8, 256>>>(inputs, ln_in_scale, ln_in_offset);     // 0
    k_wprep<<<512, 256>>>(Wk, Wv);                                         // 1
    k_init<<<352, 256>>>(slot_noise, slots_mu, slots_log_sigma, slots);    // 2
    k_mma_kv<<<dim3(4, (B_ * N_) / 128), 256, SMEM_SZ>>>();                // 3 (profiled)

    for (int it = 0; it < 3; it++) {
        k_ln256<<<352, 256>>>(slots, ln_slots_scale, ln_slots_offset);
        k_sgemm<<<dim3(32, 1), 256>>>(0, Wq, nullptr, slots, 0.0625f);
        k_zero<<<352, 256>>>();
        k_attn<<<dim3(32, 128), 256>>>();
        k_updates<<<dim3(32, 16), 256>>>();
        k_sgemm<<<dim3(32, 3), 256>>>(1, gru_wi, nullptr, slots, 1.0f);
        k_gru<<<32, 256>>>(gru_wh, gru_b, slots);
        k_ln256<<<352, 256>>>(slots, ln_mlp_scale, ln_mlp_offset);
        k_sgemm<<<dim3(32, 2), 256>>>(2, mlp_w1, mlp_b1, slots, 1.0f);
        k_sgemm<<<dim3(32, 1), 256>>>(3, mlp_w2, mlp_b2, slots, 1.0f);
    }
}

// round 4
// speedup vs baseline: 1.6665x; 1.3283x over previous
#include <cuda_runtime.h>
#include <cuda_bf16.h>
#include <stdint.h>

#define B_ 32
#define N_ 4096
#define D_ 256
#define S_ 11
#define H_ 256
#define M_ 512

// ---------------- scratch (static device globals; no allocs) ----------------
__device__ __nv_bfloat16 g_ahi[(size_t)B_*N_*D_];
__device__ __nv_bfloat16 g_alo[(size_t)B_*N_*D_];
__device__ __nv_bfloat16 g_wthi[512*256];
__device__ __nv_bfloat16 g_wtlo[512*256];
__device__ float g_kf[(size_t)B_*N_*H_];
__device__ float g_vf[(size_t)B_*N_*H_];
__device__ float g_colsum[B_*S_];
__device__ float g_q[B_*S_*H_];
__device__ float g_updraw[B_*S_*H_];
__device__ float g_gx[B_*S_*3*H_];
__device__ float g_hid[B_*S_*M_];

// ---------------- helpers ----------------
__device__ __forceinline__ uint32_t smem_u32(const void* p) {
    uint32_t a;
    asm("{ .reg .u64 t; cvta.to.shared.u64 t, %1; cvt.u32.u64 %0, t; }" : "=r"(a) : "l"(p));
    return a;
}
__device__ __forceinline__ void ldsm_x4(uint32_t& r0, uint32_t& r1, uint32_t& r2, uint32_t& r3,
                                        uint32_t addr) {
    asm volatile("ldmatrix.sync.aligned.m8n8.x4.shared.b16 {%0,%1,%2,%3}, [%4];"
                 : "=r"(r0), "=r"(r1), "=r"(r2), "=r"(r3) : "r"(addr));
}
__device__ __forceinline__ void mma16816(float* d, const uint32_t* a, const uint32_t* b) {
    asm volatile("mma.sync.aligned.m16n8k16.row.col.f32.bf16.bf16.f32 "
                 "{%0,%1,%2,%3}, {%4,%5,%6,%7}, {%8,%9}, {%0,%1,%2,%3};"
                 : "+f"(d[0]), "+f"(d[1]), "+f"(d[2]), "+f"(d[3])
                 : "r"(a[0]), "r"(a[1]), "r"(a[2]), "r"(a[3]), "r"(b[0]), "r"(b[1]));
}
__device__ __forceinline__ void cp16(uint32_t saddr, const void* g) {
    asm volatile("cp.async.cg.shared.global [%0], [%1], 16;" :: "r"(saddr), "l"(g));
}

__device__ __forceinline__ void block_reduce2(float& s, float& q) {
    #pragma unroll
    for (int off = 16; off; off >>= 1) {
        s += __shfl_xor_sync(0xffffffffu, s, off);
        q += __shfl_xor_sync(0xffffffffu, q, off);
    }
    __shared__ float ss[8], sq[8];
    int w = threadIdx.x >> 5, l = threadIdx.x & 31;
    if (l == 0) { ss[w] = s; sq[w] = q; }
    __syncthreads();
    s = 0.f; q = 0.f;
    #pragma unroll
    for (int i = 0; i < 8; i++) { s += ss[i]; q += sq[i]; }
}

// ---------------- 1) k_q: [init slots] + zero accum + LN(slots) + q = LN@Wq*scale ----------------
// one block per (b,s) row; 352 blocks.
__global__ void __launch_bounds__(256) k_q(int doinit, const float* __restrict__ noise,
                                           const float* __restrict__ mu, const float* __restrict__ ls,
                                           const float* __restrict__ g, const float* __restrict__ o,
                                           const float* __restrict__ Wq, float* __restrict__ slots)
{
    __shared__ float lns[256];
    int r = blockIdx.x, tid = threadIdx.x;
    float val;
    if (doinit) {
        val = mu[tid] + expf(ls[tid]) * noise[r * 256 + tid];
        slots[r * 256 + tid] = val;
    } else {
        val = slots[r * 256 + tid];
    }
    g_updraw[r * 256 + tid] = 0.f;          // zero this iteration's accumulators
    if (tid == 0) g_colsum[r] = 0.f;

    float s_ = val, q_ = val * val;
    block_reduce2(s_, q_);
    float muv = s_ * (1.f / 256.f);
    float var = q_ * (1.f / 256.f) - muv * muv;
    float rs = rsqrtf(var + 1e-5f);
    lns[tid] = (val - muv) * rs * g[tid] + o[tid];
    __syncthreads();

    const float* wp = Wq + tid;
    float a0 = 0.f, a1 = 0.f, a2 = 0.f, a3 = 0.f;
    #pragma unroll 4
    for (int k = 0; k < 256; k += 4) {
        a0 = fmaf(lns[k],     wp[(size_t)k * 256],       a0);
        a1 = fmaf(lns[k + 1], wp[(size_t)(k + 1) * 256], a1);
        a2 = fmaf(lns[k + 2], wp[(size_t)(k + 2) * 256], a2);
        a3 = fmaf(lns[k + 3], wp[(size_t)(k + 3) * 256], a3);
    }
    g_q[r * 256 + tid] = ((a0 + a1) + (a2 + a3)) * 0.0625f;
}

// ---------------- 2) combined input-prep + weight-prep ----------------
__global__ void __launch_bounds__(256) k_prepall(const float* __restrict__ x,
                                                 const float* __restrict__ g,
                                                 const float* __restrict__ o,
                                                 const float* __restrict__ wk,
                                                 const float* __restrict__ wv)
{
    if (blockIdx.x >= 16384) {
        int idx = (blockIdx.x - 16384) * 256 + threadIdx.x;   // 0..131071
        int j = idx >> 8;
        int k = idx & 255;
        float w = (j < 256) ? wk[k * 256 + j] : wv[k * 256 + (j - 256)];
        __nv_bfloat16 h = __float2bfloat16_rn(w);
        g_wthi[idx] = h;
        g_wtlo[idx] = __float2bfloat16_rn(w - __bfloat162float(h));
        return;
    }
    int wid = threadIdx.x >> 5, lane = threadIdx.x & 31;
    int row = blockIdx.x * 8 + wid;
    const float4* xp = (const float4*)&x[(size_t)row * 256 + lane * 8];
    float4 a = xp[0], b = xp[1];
    float s = a.x + a.y + a.z + a.w + b.x + b.y + b.z + b.w;
    float q = a.x*a.x + a.y*a.y + a.z*a.z + a.w*a.w
            + b.x*b.x + b.y*b.y + b.z*b.z + b.w*b.w;
    #pragma unroll
    for (int off = 16; off; off >>= 1) {
        s += __shfl_xor_sync(0xffffffffu, s, off);
        q += __shfl_xor_sync(0xffffffffu, q, off);
    }
    float mu = s * (1.f / 256.f);
    float var = q * (1.f / 256.f) - mu * mu;
    float rs = rsqrtf(var + 1e-5f);

    const float4* gp = (const float4*)&g[lane * 8];
    const float4* op = (const float4*)&o[lane * 8];
    float4 g0 = gp[0], g1 = gp[1], o0 = op[0], o1 = op[1];

    float v[8];
    v[0] = (a.x - mu) * rs * g0.x + o0.x;
    v[1] = (a.y - mu) * rs * g0.y + o0.y;
    v[2] = (a.z - mu) * rs * g0.z + o0.z;
    v[3] = (a.w - mu) * rs * g0.w + o0.w;
    v[4] = (b.x - mu) * rs * g1.x + o1.x;
    v[5] = (b.y - mu) * rs * g1.y + o1.y;
    v[6] = (b.z - mu) * rs * g1.z + o1.z;
    v[7] = (b.w - mu) * rs * g1.w + o1.w;

    float hf[8], lf[8];
    #pragma unroll
    for (int i = 0; i < 8; i++) {
        __nv_bfloat16 h = __float2bfloat16_rn(v[i]);
        hf[i] = __bfloat162float(h);
        lf[i] = v[i] - hf[i];
    }
    __nv_bfloat162 h01 = __floats2bfloat162_rn(hf[0], hf[1]);
    __nv_bfloat162 h23 = __floats2bfloat162_rn(hf[2], hf[3]);
    __nv_bfloat162 h45 = __floats2bfloat162_rn(hf[4], hf[5]);
    __nv_bfloat162 h67 = __floats2bfloat162_rn(hf[6], hf[7]);
    __nv_bfloat162 l01 = __floats2bfloat162_rn(lf[0], lf[1]);
    __nv_bfloat162 l23 = __floats2bfloat162_rn(lf[2], lf[3]);
    __nv_bfloat162 l45 = __floats2bfloat162_rn(lf[4], lf[5]);
    __nv_bfloat162 l67 = __floats2bfloat162_rn(lf[6], lf[7]);
    uint4 uh, ul;
    uh.x = *(uint32_t*)&h01; uh.y = *(uint32_t*)&h23; uh.z = *(uint32_t*)&h45; uh.w = *(uint32_t*)&h67;
    ul.x = *(uint32_t*)&l01; ul.y = *(uint32_t*)&l23; ul.z = *(uint32_t*)&l45; ul.w = *(uint32_t*)&l67;
    *(uint4*)&g_ahi[(size_t)row * 256 + lane * 8] = uh;
    *(uint4*)&g_alo[(size_t)row * 256 + lane * 8] = ul;
}

// ---------------- 3) mma.sync split-bf16 GEMM with cp.async double buffering ----------------
#define SM_AH 0
#define SM_AL 16384
#define SM_BH 32768
#define SM_BL 49152
#define STAGE_SZ 65536
#define SMEM_SZ (2 * STAGE_SZ)

__device__ __forceinline__ void mma_fill(uint32_t sb, int st, int rowbase, size_t jb, int kb, int tid) {
    uint32_t so = st * STAGE_SZ;
    #pragma unroll
    for (int i = 0; i < 4; i++) {
        int idx = tid + i * 256;
        int row = idx >> 3, c8 = idx & 7;
        uint32_t bo = row * 128 + c8 * 16;
        uint32_t sw = (bo ^ ((bo >> 3) & 0x70)) + so;
        size_t srcA = (size_t)(rowbase + row) * 256 + kb + c8 * 8;
        size_t srcB = jb + (size_t)row * 256 + kb + c8 * 8;
        cp16(sb + SM_AH + sw, &g_ahi[srcA]);
        cp16(sb + SM_AL + sw, &g_alo[srcA]);
        cp16(sb + SM_BH + sw, &g_wthi[srcB]);
        cp16(sb + SM_BL + sw, &g_wtlo[srcB]);
    }
    asm volatile("cp.async.commit_group;" ::: "memory");
}

__global__ void __launch_bounds__(256, 1) k_mma_kv()
{
    extern __shared__ __align__(1024) uint8_t smem[];
    uint32_t sbase = smem_u32(smem);
    int tid = threadIdx.x;
    int lane = tid & 31;
    int warp = tid >> 5;
    int wm = warp & 3;
    int wn = warp >> 2;

    int half = blockIdx.x >> 1;
    int ntile = blockIdx.x & 1;
    int rowbase = blockIdx.y * 128;
    size_t jb = ((size_t)half * 256 + ntile * 128) * 256;

    float acc[2][8][4];
    #pragma unroll
    for (int mf = 0; mf < 2; mf++)
        #pragma unroll
        for (int nf = 0; nf < 8; nf++)
            #pragma unroll
            for (int r = 0; r < 4; r++) acc[mf][nf][r] = 0.f;

    uint32_t lrow = ((lane >> 3) & 1) * 8 + (lane & 7);
    uint32_t lcol = ((lane >> 4) & 1) * 16;

    mma_fill(sbase, 0, rowbase, jb, 0, tid);
    mma_fill(sbase, 1, rowbase, jb, 64, tid);

    for (int ch = 0; ch < 4; ch++) {
        if (ch < 3) asm volatile("cp.async.wait_group 1;" ::: "memory");
        else        asm volatile("cp.async.wait_group 0;" ::: "memory");
        __syncthreads();
        uint32_t so = (ch & 1) * STAGE_SZ;

        #pragma unroll
        for (int ks = 0; ks < 4; ks++) {
            uint32_t cb = ks * 32 + lcol;
            uint32_t ah[2][4], al[2][4];
            #pragma unroll
            for (int mf = 0; mf < 2; mf++) {
                uint32_t r = wm * 32 + mf * 16 + lrow;
                uint32_t bo = r * 128 + cb;
                uint32_t sw = (bo ^ ((bo >> 3) & 0x70)) + so;
                ldsm_x4(ah[mf][0], ah[mf][1], ah[mf][2], ah[mf][3], sbase + SM_AH + sw);
                ldsm_x4(al[mf][0], al[mf][1], al[mf][2], al[mf][3], sbase + SM_AL + sw);
            }
            uint32_t bh[8][2], bl[8][2];
            #pragma unroll
            for (int g = 0; g < 4; g++) {
                uint32_t r = wn * 64 + g * 16 + lrow;
                uint32_t bo = r * 128 + cb;
                uint32_t sw = (bo ^ ((bo >> 3) & 0x70)) + so;
                uint32_t t0, t1, t2, t3;
                ldsm_x4(t0, t1, t2, t3, sbase + SM_BH + sw);
                bh[g * 2][0] = t0; bh[g * 2 + 1][0] = t1;
                bh[g * 2][1] = t2; bh[g * 2 + 1][1] = t3;
                ldsm_x4(t0, t1, t2, t3, sbase + SM_BL + sw);
                bl[g * 2][0] = t0; bl[g * 2 + 1][0] = t1;
                bl[g * 2][1] = t2; bl[g * 2 + 1][1] = t3;
            }
            #pragma unroll
            for (int mf = 0; mf < 2; mf++)
                #pragma unroll
                for (int nf = 0; nf < 8; nf++) {
                    mma16816(acc[mf][nf], ah[mf], bh[nf]);
                    mma16816(acc[mf][nf], ah[mf], bl[nf]);
                    mma16816(acc[mf][nf], al[mf], bh[nf]);
                }
        }
        __syncthreads();
        if (ch < 2) mma_fill(sbase, ch & 1, rowbase, jb, (ch + 2) * 64, tid);
    }

    float* outp = (half == 0) ? g_kf : g_vf;
    int r0 = rowbase + wm * 32 + (lane >> 2);
    int c0 = ntile * 128 + wn * 64 + (lane & 3) * 2;
    #pragma unroll
    for (int mf = 0; mf < 2; mf++)
        #pragma unroll
        for (int nf = 0; nf < 8; nf++) {
            float* d = acc[mf][nf];
            size_t base = (size_t)(r0 + mf * 16) * 256 + c0 + nf * 8;
            *(float2*)&outp[base] = make_float2(d[0], d[1]);
            *(float2*)&outp[base + 8 * 256] = make_float2(d[2], d[3]);
        }
}

// ---------------- 4) fused attention: logits + softmax + eps + U accum + colsum ----------------
// grid (32, 16): batch b, 256-row chunk. U kept in registers (column tid), p staged in smem.
__global__ void __launch_bounds__(256) k_attn_upd()
{
    __shared__ float qs[11][256];
    __shared__ __align__(16) float ps[32][12];
    __shared__ float wcs[8][12];
    int b = blockIdx.x, chunk = blockIdx.y, tid = threadIdx.x;
    int warp = tid >> 5, lane = tid & 31;

    for (int i = tid; i < 11 * 256; i += 256) qs[i >> 8][i & 255] = g_q[b * 2816 + i];

    float U[11], csr[11];
    #pragma unroll
    for (int s = 0; s < 11; s++) { U[s] = 0.f; csr[s] = 0.f; }
    int nb = chunk * 256;
    __syncthreads();

    for (int sub = 0; sub < 8; sub++) {
        // phase A: logits + softmax for 32 rows (4 per warp)
        #pragma unroll
        for (int rr = 0; rr < 4; rr++) {
            int nl = sub * 32 + warp * 4 + rr;
            const float* kfp = &g_kf[((size_t)(b * 4096 + nb + nl)) * 256];
            float acc[11];
            #pragma unroll
            for (int s = 0; s < 11; s++) acc[s] = 0.f;
            #pragma unroll
            for (int i = 0; i < 8; i++) {
                float xv = kfp[i * 32 + lane];
                #pragma unroll
                for (int s = 0; s < 11; s++) acc[s] += xv * qs[s][i * 32 + lane];
            }
            #pragma unroll
            for (int off = 16; off; off >>= 1) {
                #pragma unroll
                for (int s = 0; s < 11; s++) acc[s] += __shfl_xor_sync(0xffffffffu, acc[s], off);
            }
            // uniform across lanes now
            float m = acc[0];
            #pragma unroll
            for (int s = 1; s < 11; s++) m = fmaxf(m, acc[s]);
            float e[11], sum = 0.f;
            #pragma unroll
            for (int s = 0; s < 11; s++) { e[s] = expf(acc[s] - m); sum += e[s]; }
            float inv = 1.f / sum;
            #pragma unroll
            for (int s = 0; s < 11; s++) {
                float p = e[s] * inv + 1e-8f;
                csr[s] += p;
                if (lane == 0) ps[warp * 4 + rr][s] = p;
            }
        }
        __syncthreads();
        // phase B: U[s] += p[n][s] * vf[n][tid]
        const float* vp = &g_vf[((size_t)(b * 4096 + nb + sub * 32)) * 256 + tid];
        #pragma unroll 4
        for (int n = 0; n < 32; n++) {
            float v = vp[(size_t)n * 256];
            const float4* p4 = (const float4*)&ps[n][0];
            float4 A0 = p4[0], A1 = p4[1], A2 = p4[2];
            U[0] += A0.x * v; U[1] += A0.y * v; U[2]  += A0.z * v; U[3] += A0.w * v;
            U[4] += A1.x * v; U[5] += A1.y * v; U[6]  += A1.z * v; U[7] += A1.w * v;
            U[8] += A2.x * v; U[9] += A2.y * v; U[10] += A2.z * v;
        }
        __syncthreads();
    }

    float* up = &g_updraw[((size_t)b * 11) * 256 + tid];
    #pragma unroll
    for (int s = 0; s < 11; s++) atomicAdd(&up[s * 256], U[s]);

    // csr uniform across lanes within a warp; note phase A ran per-warp so csr differs per warp
    if (lane == 0) {
        #pragma unroll
        for (int s = 0; s < 11; s++) wcs[warp][s] = csr[s];
    }
    __syncthreads();
    if (tid < 11) {
        float c = 0.f;
        #pragma unroll
        for (int w = 0; w < 8; w++) c += wcs[w][tid];
        atomicAdd(&g_colsum[b * 11 + tid], c);
    }
}

// ---------------- 5) gx = (U / colsum) @ gru_wi ----------------
__global__ void __launch_bounds__(256) k_gx(const float* __restrict__ wi)
{
    __shared__ __align__(16) float ins[256 * 12];
    __shared__ float sinv[11];
    int b = blockIdx.x, jt = blockIdx.y, tid = threadIdx.x;
    if (tid < 11) sinv[tid] = 1.f / g_colsum[b * 11 + tid];
    __syncthreads();
    for (int i = tid; i < 11 * 256; i += 256) {
        int s = i >> 8, k = i & 255;
        ins[k * 12 + s] = g_updraw[((size_t)b * 11 + s) * 256 + k] * sinv[s];
    }
    __syncthreads();

    int j = jt * 256 + tid;
    float acc[11];
    #pragma unroll
    for (int s = 0; s < 11; s++) acc[s] = 0.f;
    const float* wp = wi + j;
    #pragma unroll 2
    for (int k = 0; k < 256; k++) {
        float w = wp[(size_t)k * 768];
        const float4* s4 = (const float4*)&ins[k * 12];
        float4 A0 = s4[0], A1 = s4[1], A2 = s4[2];
        acc[0] += A0.x * w; acc[1] += A0.y * w; acc[2]  += A0.z * w; acc[3] += A0.w * w;
        acc[4] += A1.x * w; acc[5] += A1.y * w; acc[6]  += A1.z * w; acc[7] += A1.w * w;
        acc[8] += A2.x * w; acc[9] += A2.y * w; acc[10] += A2.z * w;
    }
    #pragma unroll
    for (int s = 0; s < 11; s++)
        g_gx[((size_t)b * 11 + s) * 768 + j] = acc[s];
}

// ---------------- 6) GRU scan (one CTA per batch), 4-way split chains ----------------
__global__ void __launch_bounds__(256) k_gru(const float* __restrict__ wh,
                                             const float* __restrict__ gb,
                                             float* __restrict__ slots)
{
    __shared__ float hs[256], rh[256];
    int b = blockIdx.x;
    int tid = threadIdx.x;
    hs[tid] = 0.f;
    float bz = gb[tid], br = gb[256 + tid], ba = gb[512 + tid];
    __syncthreads();

    for (int s = 0; s < 11; s++) {
        const float* gx = &g_gx[((size_t)b * 11 + s) * 768];
        const float* wz = wh + tid;
        const float* wr = wh + 256 + tid;
        float az0 = gx[tid] + bz, az1 = 0.f, az2 = 0.f, az3 = 0.f;
        float ar0 = gx[256 + tid] + br, ar1 = 0.f, ar2 = 0.f, ar3 = 0.f;
        #pragma unroll 2
        for (int k = 0; k < 256; k += 4) {
            float h0 = hs[k], h1 = hs[k + 1], h2 = hs[k + 2], h3 = hs[k + 3];
            az0 = fmaf(h0, wz[(size_t)k * 768],       az0);
            az1 = fmaf(h1, wz[(size_t)(k + 1) * 768], az1);
            az2 = fmaf(h2, wz[(size_t)(k + 2) * 768], az2);
            az3 = fmaf(h3, wz[(size_t)(k + 3) * 768], az3);
            ar0 = fmaf(h0, wr[(size_t)k * 768],       ar0);
            ar1 = fmaf(h1, wr[(size_t)(k + 1) * 768], ar1);
            ar2 = fmaf(h2, wr[(size_t)(k + 2) * 768], ar2);
            ar3 = fmaf(h3, wr[(size_t)(k + 3) * 768], ar3);
        }
        float az = (az0 + az1) + (az2 + az3);
        float ar = (ar0 + ar1) + (ar2 + ar3);
        float z = 1.f / (1.f + expf(-az));
        float r = 1.f / (1.f + expf(-ar));
        float hold = hs[tid];
        rh[tid] = r * hold;
        __syncthreads();
        const float* wa = wh + 512 + tid;
        float aa0 = gx[512 + tid] + ba, aa1 = 0.f, aa2 = 0.f, aa3 = 0.f;
        #pragma unroll 2
        for (int k = 0; k < 256; k += 4) {
            aa0 = fmaf(rh[k],     wa[(size_t)k * 768],       aa0);
            aa1 = fmaf(rh[k + 1], wa[(size_t)(k + 1) * 768], aa1);
            aa2 = fmaf(rh[k + 2], wa[(size_t)(k + 2) * 768], aa2);
            aa3 = fmaf(rh[k + 3], wa[(size_t)(k + 3) * 768], aa3);
        }
        float aa = (aa0 + aa1) + (aa2 + aa3);
        float a = tanhf(aa);
        float hn = (1.f - z) * hold + z * a;
        slots[((size_t)b * 11 + s) * 256 + tid] = hn;
        hs[tid] = hn;
        __syncthreads();
    }
}

// ---------------- 7) mlp1: hid = relu(LN(slots) @ w1 + b1) ----------------
__global__ void __launch_bounds__(256) k_mlp1(const float* __restrict__ slots,
                                              const float* __restrict__ g, const float* __restrict__ o,
                                              const float* __restrict__ w1, const float* __restrict__ b1)
{
    __shared__ float lns[256];
    int r = blockIdx.x, tid = threadIdx.x;
    float val = slots[r * 256 + tid];
    float s_ = val, q_ = val * val;
    block_reduce2(s_, q_);
    float muv = s_ * (1.f / 256.f);
    float var = q_ * (1.f / 256.f) - muv * muv;
    float rs = rsqrtf(var + 1e-5f);
    lns[tid] = (val - muv) * rs * g[tid] + o[tid];
    __syncthreads();

    const float2* wp = (const float2*)&w1[tid * 2];
    float ax0 = 0.f, ay0 = 0.f, ax1 = 0.f, ay1 = 0.f;
    #pragma unroll 4
    for (int k = 0; k < 256; k += 2) {
        float l0 = lns[k], l1 = lns[k + 1];
        float2 w0 = wp[(size_t)k * 256];         // w1[k*512 + tid*2]
        float2 w1v = wp[(size_t)(k + 1) * 256];
        ax0 = fmaf(l0, w0.x, ax0); ay0 = fmaf(l0, w0.y, ay0);
        ax1 = fmaf(l1, w1v.x, ax1); ay1 = fmaf(l1, w1v.y, ay1);
    }
    float2 bb = *(const float2*)&b1[tid * 2];
    float2 hv;
    hv.x = fmaxf(ax0 + ax1 + bb.x, 0.f);
    hv.y = fmaxf(ay0 + ay1 + bb.y, 0.f);
    *(float2*)&g_hid[(size_t)r * 512 + tid * 2] = hv;
}

// ---------------- 8) mlp2: slots += hid @ w2 + b2 ----------------
__global__ void __launch_bounds__(256) k_mlp2(const float* __restrict__ w2,
                                              const float* __restrict__ b2,
                                              float* __restrict__ slots)
{
    __shared__ float sh[512];
    int r = blockIdx.x, tid = threadIdx.x;
    sh[tid] = g_hid[(size_t)r * 512 + tid];
    sh[tid + 256] = g_hid[(size_t)r * 512 + tid + 256];
    __syncthreads();

    const float* wp = w2 + tid;
    float a0 = 0.f, a1 = 0.f, a2 = 0.f, a3 = 0.f;
    #pragma unroll 4
    for (int k = 0; k < 512; k += 4) {
        a0 = fmaf(sh[k],     wp[(size_t)k * 256],       a0);
        a1 = fmaf(sh[k + 1], wp[(size_t)(k + 1) * 256], a1);
        a2 = fmaf(sh[k + 2], wp[(size_t)(k + 2) * 256], a2);
        a3 = fmaf(sh[k + 3], wp[(size_t)(k + 3) * 256], a3);
    }
    slots[r * 256 + tid] += ((a0 + a1) + (a2 + a3)) + b2[tid];
}

// ---------------- host launch ----------------
extern "C" void kernel_launch(void* const* d_in, const int* in_sizes, int n_in,
                              void* d_out, int out_size)
{
    const float* inputs          = (const float*)d_in[0];
    const float* slot_noise      = (const float*)d_in[1];
    const float* ln_in_scale     = (const float*)d_in[2];
    const float* ln_in_offset    = (const float*)d_in[3];
    const float* ln_slots_scale  = (const float*)d_in[4];
    const float* ln_slots_offset = (const float*)d_in[5];
    const float* ln_mlp_scale    = (const float*)d_in[6];
    const float* ln_mlp_offset   = (const float*)d_in[7];
    const float* slots_mu        = (const float*)d_in[8];
    const float* slots_log_sigma = (const float*)d_in[9];
    const float* Wq              = (const float*)d_in[10];
    const float* Wk              = (const float*)d_in[11];
    const float* Wv              = (const float*)d_in[12];
    const float* gru_wi          = (const float*)d_in[13];
    const float* gru_wh          = (const float*)d_in[14];
    const float* gru_b           = (const float*)d_in[15];
    const float* mlp_w1          = (const float*)d_in[16];
    const float* mlp_b1          = (const float*)d_in[17];
    const float* mlp_w2          = (const float*)d_in[18];
    const float* mlp_b2          = (const float*)d_in[19];
    float* slots = (float*)d_out;

    (void)in_sizes; (void)n_in; (void)out_size;

    cudaFuncSetAttribute(k_mma_kv, cudaFuncAttributeMaxDynamicSharedMemorySize, SMEM_SZ);

    // launch index 0..3 chosen so ncu (-s) lands on k_attn_upd at index 3
    k_q<<<352, 256>>>(1, slot_noise, slots_mu, slots_log_sigma,
                      ln_slots_scale, ln_slots_offset, Wq, slots);        // 0
    k_prepall<<<16384 + 512, 256>>>(inputs, ln_in_scale, ln_in_offset, Wk, Wv); // 1
    k_mma_kv<<<dim3(4, (B_ * N_) / 128), 256, SMEM_SZ>>>();               // 2
    k_attn_upd<<<dim3(32, 16), 256>>>();                                  // 3 (profiled)
    k_gx<<<dim3(32, 3), 256>>>(gru_wi);
    k_gru<<<32, 256>>>(gru_wh, gru_b, slots);
    k_mlp1<<<352, 256>>>(slots, ln_mlp_scale, ln_mlp_offset, mlp_w1, mlp_b1);
    k_mlp2<<<352, 256>>>(mlp_w2, mlp_b2, slots);

    for (int it = 1; it < 3; it++) {
        k_q<<<352, 256>>>(0, slot_noise, slots_mu, slots_log_sigma,
                          ln_slots_scale, ln_slots_offset, Wq, slots);
        k_attn_upd<<<dim3(32, 16), 256>>>();
        k_gx<<<dim3(32, 3), 256>>>(gru_wi);
        k_gru<<<32, 256>>>(gru_wh, gru_b, slots);
        k_mlp1<<<352, 256>>>(slots, ln_mlp_scale, ln_mlp_offset, mlp_w1, mlp_b1);
        k_mlp2<<<352, 256>>>(mlp_w2, mlp_b2, slots);
    }
}

// round 5
// speedup vs baseline: 2.4618x; 1.4773x over previous
#include <cuda_runtime.h>
#include <cuda_bf16.h>
#include <stdint.h>

#define B_ 32
#define N_ 4096
#define D_ 256
#define S_ 11
#define H_ 256
#define M_ 512

// ---------------- scratch (static device globals; no allocs) ----------------
__device__ __nv_bfloat16 g_ahi[(size_t)B_*N_*D_];
__device__ __nv_bfloat16 g_alo[(size_t)B_*N_*D_];
__device__ __nv_bfloat16 g_wthi[512*256];
__device__ __nv_bfloat16 g_wtlo[512*256];
__device__ float g_kf[(size_t)B_*N_*H_];
__device__ float g_vf[(size_t)B_*N_*H_];
__device__ float g_colsum[B_*S_];
__device__ float g_q[B_*S_*H_];
__device__ float g_updraw[B_*S_*H_];
__device__ float g_gx[B_*S_*3*H_];

// ---------------- helpers ----------------
__device__ __forceinline__ uint32_t smem_u32(const void* p) {
    uint32_t a;
    asm("{ .reg .u64 t; cvta.to.shared.u64 t, %1; cvt.u32.u64 %0, t; }" : "=r"(a) : "l"(p));
    return a;
}
__device__ __forceinline__ void ldsm_x4(uint32_t& r0, uint32_t& r1, uint32_t& r2, uint32_t& r3,
                                        uint32_t addr) {
    asm volatile("ldmatrix.sync.aligned.m8n8.x4.shared.b16 {%0,%1,%2,%3}, [%4];"
                 : "=r"(r0), "=r"(r1), "=r"(r2), "=r"(r3) : "r"(addr));
}
__device__ __forceinline__ void mma16816(float* d, const uint32_t* a, const uint32_t* b) {
    asm volatile("mma.sync.aligned.m16n8k16.row.col.f32.bf16.bf16.f32 "
                 "{%0,%1,%2,%3}, {%4,%5,%6,%7}, {%8,%9}, {%0,%1,%2,%3};"
                 : "+f"(d[0]), "+f"(d[1]), "+f"(d[2]), "+f"(d[3])
                 : "r"(a[0]), "r"(a[1]), "r"(a[2]), "r"(a[3]), "r"(b[0]), "r"(b[1]));
}
__device__ __forceinline__ void cp16(uint32_t saddr, const void* g) {
    asm volatile("cp.async.cg.shared.global [%0], [%1], 16;" :: "r"(saddr), "l"(g));
}
__device__ __forceinline__ void cp_commit() {
    asm volatile("cp.async.commit_group;" ::: "memory");
}
__device__ __forceinline__ void cp_wait1() {
    asm volatile("cp.async.wait_group 1;" ::: "memory");
}
__device__ __forceinline__ void cp_wait0() {
    asm volatile("cp.async.wait_group 0;" ::: "memory");
}

__device__ __forceinline__ void block_reduce2(float& s, float& q) {
    #pragma unroll
    for (int off = 16; off; off >>= 1) {
        s += __shfl_xor_sync(0xffffffffu, s, off);
        q += __shfl_xor_sync(0xffffffffu, q, off);
    }
    __shared__ float ss[8], sq[8];
    int w = threadIdx.x >> 5, l = threadIdx.x & 31;
    if (l == 0) { ss[w] = s; sq[w] = q; }
    __syncthreads();
    s = 0.f; q = 0.f;
    #pragma unroll
    for (int i = 0; i < 8; i++) { s += ss[i]; q += sq[i]; }
}

// ---------------- 1) k_q: [init slots] + zero accum + LN(slots) + q = LN@Wq*scale ----------------
__global__ void __launch_bounds__(256) k_q(int doinit, const float* __restrict__ noise,
                                           const float* __restrict__ mu, const float* __restrict__ ls,
                                           const float* __restrict__ g, const float* __restrict__ o,
                                           const float* __restrict__ Wq, float* __restrict__ slots)
{
    __shared__ float lns[256];
    int r = blockIdx.x, tid = threadIdx.x;
    float val;
    if (doinit) {
        val = mu[tid] + expf(ls[tid]) * noise[r * 256 + tid];
        slots[r * 256 + tid] = val;
    } else {
        val = slots[r * 256 + tid];
    }
    g_updraw[r * 256 + tid] = 0.f;
    if (tid == 0) g_colsum[r] = 0.f;

    float s_ = val, q_ = val * val;
    block_reduce2(s_, q_);
    float muv = s_ * (1.f / 256.f);
    float var = q_ * (1.f / 256.f) - muv * muv;
    float rs = rsqrtf(var + 1e-5f);
    lns[tid] = (val - muv) * rs * g[tid] + o[tid];
    __syncthreads();

    const float* wp = Wq + tid;
    float a0 = 0.f, a1 = 0.f, a2 = 0.f, a3 = 0.f;
    #pragma unroll 4
    for (int k = 0; k < 256; k += 4) {
        a0 = fmaf(lns[k],     wp[(size_t)k * 256],       a0);
        a1 = fmaf(lns[k + 1], wp[(size_t)(k + 1) * 256], a1);
        a2 = fmaf(lns[k + 2], wp[(size_t)(k + 2) * 256], a2);
        a3 = fmaf(lns[k + 3], wp[(size_t)(k + 3) * 256], a3);
    }
    g_q[r * 256 + tid] = ((a0 + a1) + (a2 + a3)) * 0.0625f;
}

// ---------------- 2) combined input-prep + weight-prep ----------------
__global__ void __launch_bounds__(256) k_prepall(const float* __restrict__ x,
                                                 const float* __restrict__ g,
                                                 const float* __restrict__ o,
                                                 const float* __restrict__ wk,
                                                 const float* __restrict__ wv)
{
    if (blockIdx.x >= 16384) {
        int idx = (blockIdx.x - 16384) * 256 + threadIdx.x;
        int j = idx >> 8;
        int k = idx & 255;
        float w = (j < 256) ? wk[k * 256 + j] : wv[k * 256 + (j - 256)];
        __nv_bfloat16 h = __float2bfloat16_rn(w);
        g_wthi[idx] = h;
        g_wtlo[idx] = __float2bfloat16_rn(w - __bfloat162float(h));
        return;
    }
    int wid = threadIdx.x >> 5, lane = threadIdx.x & 31;
    int row = blockIdx.x * 8 + wid;
    const float4* xp = (const float4*)&x[(size_t)row * 256 + lane * 8];
    float4 a = xp[0], b = xp[1];
    float s = a.x + a.y + a.z + a.w + b.x + b.y + b.z + b.w;
    float q = a.x*a.x + a.y*a.y + a.z*a.z + a.w*a.w
            + b.x*b.x + b.y*b.y + b.z*b.z + b.w*b.w;
    #pragma unroll
    for (int off = 16; off; off >>= 1) {
        s += __shfl_xor_sync(0xffffffffu, s, off);
        q += __shfl_xor_sync(0xffffffffu, q, off);
    }
    float mu = s * (1.f / 256.f);
    float var = q * (1.f / 256.f) - mu * mu;
    float rs = rsqrtf(var + 1e-5f);

    const float4* gp = (const float4*)&g[lane * 8];
    const float4* op = (const float4*)&o[lane * 8];
    float4 g0 = gp[0], g1 = gp[1], o0 = op[0], o1 = op[1];

    float v[8];
    v[0] = (a.x - mu) * rs * g0.x + o0.x;
    v[1] = (a.y - mu) * rs * g0.y + o0.y;
    v[2] = (a.z - mu) * rs * g0.z + o0.z;
    v[3] = (a.w - mu) * rs * g0.w + o0.w;
    v[4] = (b.x - mu) * rs * g1.x + o1.x;
    v[5] = (b.y - mu) * rs * g1.y + o1.y;
    v[6] = (b.z - mu) * rs * g1.z + o1.z;
    v[7] = (b.w - mu) * rs * g1.w + o1.w;

    float hf[8], lf[8];
    #pragma unroll
    for (int i = 0; i < 8; i++) {
        __nv_bfloat16 h = __float2bfloat16_rn(v[i]);
        hf[i] = __bfloat162float(h);
        lf[i] = v[i] - hf[i];
    }
    __nv_bfloat162 h01 = __floats2bfloat162_rn(hf[0], hf[1]);
    __nv_bfloat162 h23 = __floats2bfloat162_rn(hf[2], hf[3]);
    __nv_bfloat162 h45 = __floats2bfloat162_rn(hf[4], hf[5]);
    __nv_bfloat162 h67 = __floats2bfloat162_rn(hf[6], hf[7]);
    __nv_bfloat162 l01 = __floats2bfloat162_rn(lf[0], lf[1]);
    __nv_bfloat162 l23 = __floats2bfloat162_rn(lf[2], lf[3]);
    __nv_bfloat162 l45 = __floats2bfloat162_rn(lf[4], lf[5]);
    __nv_bfloat162 l67 = __floats2bfloat162_rn(lf[6], lf[7]);
    uint4 uh, ul;
    uh.x = *(uint32_t*)&h01; uh.y = *(uint32_t*)&h23; uh.z = *(uint32_t*)&h45; uh.w = *(uint32_t*)&h67;
    ul.x = *(uint32_t*)&l01; ul.y = *(uint32_t*)&l23; ul.z = *(uint32_t*)&l45; ul.w = *(uint32_t*)&l67;
    *(uint4*)&g_ahi[(size_t)row * 256 + lane * 8] = uh;
    *(uint4*)&g_alo[(size_t)row * 256 + lane * 8] = ul;
}

// ---------------- 3) mma.sync split-bf16 GEMM with cp.async double buffering ----------------
#define SM_AH 0
#define SM_AL 16384
#define SM_BH 32768
#define SM_BL 49152
#define STAGE_SZ 65536
#define SMEM_SZ (2 * STAGE_SZ)

__device__ __forceinline__ void mma_fill(uint32_t sb, int st, int rowbase, size_t jb, int kb, int tid) {
    uint32_t so = st * STAGE_SZ;
    #pragma unroll
    for (int i = 0; i < 4; i++) {
        int idx = tid + i * 256;
        int row = idx >> 3, c8 = idx & 7;
        uint32_t bo = row * 128 + c8 * 16;
        uint32_t sw = (bo ^ ((bo >> 3) & 0x70)) + so;
        size_t srcA = (size_t)(rowbase + row) * 256 + kb + c8 * 8;
        size_t srcB = jb + (size_t)row * 256 + kb + c8 * 8;
        cp16(sb + SM_AH + sw, &g_ahi[srcA]);
        cp16(sb + SM_AL + sw, &g_alo[srcA]);
        cp16(sb + SM_BH + sw, &g_wthi[srcB]);
        cp16(sb + SM_BL + sw, &g_wtlo[srcB]);
    }
    cp_commit();
}

__global__ void __launch_bounds__(256, 1) k_mma_kv()
{
    extern __shared__ __align__(1024) uint8_t smem[];
    uint32_t sbase = smem_u32(smem);
    int tid = threadIdx.x;
    int lane = tid & 31;
    int warp = tid >> 5;
    int wm = warp & 3;
    int wn = warp >> 2;

    int half = blockIdx.x >> 1;
    int ntile = blockIdx.x & 1;
    int rowbase = blockIdx.y * 128;
    size_t jb = ((size_t)half * 256 + ntile * 128) * 256;

    float acc[2][8][4];
    #pragma unroll
    for (int mf = 0; mf < 2; mf++)
        #pragma unroll
        for (int nf = 0; nf < 8; nf++)
            #pragma unroll
            for (int r = 0; r < 4; r++) acc[mf][nf][r] = 0.f;

    uint32_t lrow = ((lane >> 3) & 1) * 8 + (lane & 7);
    uint32_t lcol = ((lane >> 4) & 1) * 16;

    mma_fill(sbase, 0, rowbase, jb, 0, tid);
    mma_fill(sbase, 1, rowbase, jb, 64, tid);

    for (int ch = 0; ch < 4; ch++) {
        if (ch < 3) cp_wait1();
        else        cp_wait0();
        __syncthreads();
        uint32_t so = (ch & 1) * STAGE_SZ;

        #pragma unroll
        for (int ks = 0; ks < 4; ks++) {
            uint32_t cb = ks * 32 + lcol;
            uint32_t ah[2][4], al[2][4];
            #pragma unroll
            for (int mf = 0; mf < 2; mf++) {
                uint32_t r = wm * 32 + mf * 16 + lrow;
                uint32_t bo = r * 128 + cb;
                uint32_t sw = (bo ^ ((bo >> 3) & 0x70)) + so;
                ldsm_x4(ah[mf][0], ah[mf][1], ah[mf][2], ah[mf][3], sbase + SM_AH + sw);
                ldsm_x4(al[mf][0], al[mf][1], al[mf][2], al[mf][3], sbase + SM_AL + sw);
            }
            uint32_t bh[8][2], bl[8][2];
            #pragma unroll
            for (int g = 0; g < 4; g++) {
                uint32_t r = wn * 64 + g * 16 + lrow;
                uint32_t bo = r * 128 + cb;
                uint32_t sw = (bo ^ ((bo >> 3) & 0x70)) + so;
                uint32_t t0, t1, t2, t3;
                ldsm_x4(t0, t1, t2, t3, sbase + SM_BH + sw);
                bh[g * 2][0] = t0; bh[g * 2 + 1][0] = t1;
                bh[g * 2][1] = t2; bh[g * 2 + 1][1] = t3;
                ldsm_x4(t0, t1, t2, t3, sbase + SM_BL + sw);
                bl[g * 2][0] = t0; bl[g * 2 + 1][0] = t1;
                bl[g * 2][1] = t2; bl[g * 2 + 1][1] = t3;
            }
            #pragma unroll
            for (int mf = 0; mf < 2; mf++)
                #pragma unroll
                for (int nf = 0; nf < 8; nf++) {
                    mma16816(acc[mf][nf], ah[mf], bh[nf]);
                    mma16816(acc[mf][nf], ah[mf], bl[nf]);
                    mma16816(acc[mf][nf], al[mf], bh[nf]);
                }
        }
        __syncthreads();
        if (ch < 2) mma_fill(sbase, ch & 1, rowbase, jb, (ch + 2) * 64, tid);
    }

    float* outp = (half == 0) ? g_kf : g_vf;
    int r0 = rowbase + wm * 32 + (lane >> 2);
    int c0 = ntile * 128 + wn * 64 + (lane & 3) * 2;
    #pragma unroll
    for (int mf = 0; mf < 2; mf++)
        #pragma unroll
        for (int nf = 0; nf < 8; nf++) {
            float* d = acc[mf][nf];
            size_t base = (size_t)(r0 + mf * 16) * 256 + c0 + nf * 8;
            *(float2*)&outp[base] = make_float2(d[0], d[1]);
            *(float2*)&outp[base + 8 * 256] = make_float2(d[2], d[3]);
        }
}

// ---------------- 4) fused attention: logits + softmax + eps + U accum + colsum ----------------
__global__ void __launch_bounds__(256, 2) k_attn_upd()
{
    __shared__ __align__(16) float qs[11][256];
    __shared__ __align__(16) float ps[32][12];
    __shared__ float wcs[8][12];
    int b = blockIdx.x, chunk = blockIdx.y, tid = threadIdx.x;
    int warp = tid >> 5, lane = tid & 31;

    for (int i = tid; i < 11 * 256; i += 256) qs[i >> 8][i & 255] = g_q[b * 2816 + i];

    float U[11], csr[11];
    #pragma unroll
    for (int s = 0; s < 11; s++) { U[s] = 0.f; csr[s] = 0.f; }
    int nb = chunk * 256;
    __syncthreads();

    for (int sub = 0; sub < 8; sub++) {
        // phase A: logits + softmax for 32 rows (4 per warp), float4 vectorized
        #pragma unroll
        for (int rr = 0; rr < 4; rr++) {
            int nl = sub * 32 + warp * 4 + rr;
            const float4* kf4 = (const float4*)&g_kf[((size_t)(b * 4096 + nb + nl)) * 256];
            float acc[11];
            #pragma unroll
            for (int s = 0; s < 11; s++) acc[s] = 0.f;
            #pragma unroll
            for (int i = 0; i < 2; i++) {
                float4 kv = kf4[i * 32 + lane];
                #pragma unroll
                for (int s = 0; s < 11; s++) {
                    float4 qv = *(const float4*)&qs[s][(i * 32 + lane) * 4];
                    acc[s] += kv.x * qv.x + kv.y * qv.y + kv.z * qv.z + kv.w * qv.w;
                }
            }
            #pragma unroll
            for (int off = 16; off; off >>= 1) {
                #pragma unroll
                for (int s = 0; s < 11; s++) acc[s] += __shfl_xor_sync(0xffffffffu, acc[s], off);
            }
            float m = acc[0];
            #pragma unroll
            for (int s = 1; s < 11; s++) m = fmaxf(m, acc[s]);
            float e[11], sum = 0.f;
            #pragma unroll
            for (int s = 0; s < 11; s++) { e[s] = expf(acc[s] - m); sum += e[s]; }
            float inv = 1.f / sum;
            #pragma unroll
            for (int s = 0; s < 11; s++) {
                float p = e[s] * inv + 1e-8f;
                csr[s] += p;
                if (lane == 0) ps[warp * 4 + rr][s] = p;
            }
        }
        __syncthreads();
        // phase B: U[s] += p[n][s] * vf[n][tid]
        const float* vp = &g_vf[((size_t)(b * 4096 + nb + sub * 32)) * 256 + tid];
        #pragma unroll 4
        for (int n = 0; n < 32; n++) {
            float v = vp[(size_t)n * 256];
            const float4* p4 = (const float4*)&ps[n][0];
            float4 A0 = p4[0], A1 = p4[1], A2 = p4[2];
            U[0] += A0.x * v; U[1] += A0.y * v; U[2]  += A0.z * v; U[3] += A0.w * v;
            U[4] += A1.x * v; U[5] += A1.y * v; U[6]  += A1.z * v; U[7] += A1.w * v;
            U[8] += A2.x * v; U[9] += A2.y * v; U[10] += A2.z * v;
        }
        __syncthreads();
    }

    float* up = &g_updraw[((size_t)b * 11) * 256 + tid];
    #pragma unroll
    for (int s = 0; s < 11; s++) atomicAdd(&up[s * 256], U[s]);

    if (lane == 0) {
        #pragma unroll
        for (int s = 0; s < 11; s++) wcs[warp][s] = csr[s];
    }
    __syncthreads();
    if (tid < 11) {
        float c = 0.f;
        #pragma unroll
        for (int w = 0; w < 8; w++) c += wcs[w][tid];
        atomicAdd(&g_colsum[b * 11 + tid], c);
    }
}

// ---------------- 5) gx = (U / colsum) @ gru_wi ----------------
__global__ void __launch_bounds__(256) k_gx(const float* __restrict__ wi)
{
    __shared__ __align__(16) float ins[256 * 12];
    __shared__ float sinv[11];
    int b = blockIdx.x, jt = blockIdx.y, tid = threadIdx.x;
    if (tid < 11) sinv[tid] = 1.f / g_colsum[b * 11 + tid];
    __syncthreads();
    for (int i = tid; i < 11 * 256; i += 256) {
        int s = i >> 8, k = i & 255;
        ins[k * 12 + s] = g_updraw[((size_t)b * 11 + s) * 256 + k] * sinv[s];
    }
    __syncthreads();

    int j = jt * 256 + tid;
    float acc[11];
    #pragma unroll
    for (int s = 0; s < 11; s++) acc[s] = 0.f;
    const float* wp = wi + j;
    #pragma unroll 2
    for (int k = 0; k < 256; k++) {
        float w = wp[(size_t)k * 768];
        const float4* s4 = (const float4*)&ins[k * 12];
        float4 A0 = s4[0], A1 = s4[1], A2 = s4[2];
        acc[0] += A0.x * w; acc[1] += A0.y * w; acc[2]  += A0.z * w; acc[3] += A0.w * w;
        acc[4] += A1.x * w; acc[5] += A1.y * w; acc[6]  += A1.z * w; acc[7] += A1.w * w;
        acc[8] += A2.x * w; acc[9] += A2.y * w; acc[10] += A2.z * w;
    }
    #pragma unroll
    for (int s = 0; s < 11; s++)
        g_gx[((size_t)b * 11 + s) * 768 + j] = acc[s];
}

// ---------------- 6) GRU scan, cp.async smem-staged weights ----------------
// dynamic smem floats: [0:256) hs | [256:512) rh | [512 : 512+2*32*512) swzr | then 2*32*256 swa
#define GRU_SMEM ((512 + 2 * 32 * 512 + 2 * 32 * 256) * 4)

__global__ void __launch_bounds__(256) k_gru(const float* __restrict__ wh,
                                             const float* __restrict__ gb,
                                             float* __restrict__ slots)
{
    extern __shared__ __align__(16) float sm[];
    float* hs = sm;
    float* rh = sm + 256;
    float* swzr = sm + 512;
    float* swa  = sm + 512 + 2 * 32 * 512;
    uint32_t szr_u = smem_u32(swzr);
    uint32_t sa_u  = smem_u32(swa);

    int b = blockIdx.x;
    int tid = threadIdx.x;
    hs[tid] = 0.f;
    float bz = gb[tid], br = gb[256 + tid], ba = gb[512 + tid];
    __syncthreads();

    for (int s = 0; s < 11; s++) {
        const float* gx = &g_gx[((size_t)b * 11 + s) * 768];
        float az0 = gx[tid] + bz, az1 = 0.f;
        float ar0 = gx[256 + tid] + br, ar1 = 0.f;

        // ---- zr pass: 8 chunks of 32 k-rows, cols [0,512) ----
        {
            // prologue: chunk 0 -> stage 0
            #pragma unroll
            for (int i = 0; i < 16; i++) {
                int idx = tid + i * 256;
                int row = idx >> 7, c4 = idx & 127;
                cp16(szr_u + (row * 512 + c4 * 4) * 4, wh + (size_t)row * 768 + c4 * 4);
            }
            cp_commit();
            for (int c = 0; c < 8; c++) {
                if (c < 7) {
                    int st = (c + 1) & 1;
                    int k0 = (c + 1) * 32;
                    #pragma unroll
                    for (int i = 0; i < 16; i++) {
                        int idx = tid + i * 256;
                        int row = idx >> 7, c4 = idx & 127;
                        cp16(szr_u + (st * 32 * 512 + row * 512 + c4 * 4) * 4,
                             wh + (size_t)(k0 + row) * 768 + c4 * 4);
                    }
                    cp_commit();
                    cp_wait1();
                } else {
                    cp_wait0();
                }
                __syncthreads();
                const float* w = swzr + (c & 1) * 32 * 512;
                int kb = c * 32;
                #pragma unroll 4
                for (int kk = 0; kk < 32; kk += 2) {
                    float h0 = hs[kb + kk], h1 = hs[kb + kk + 1];
                    az0 = fmaf(h0, w[kk * 512 + tid], az0);
                    ar0 = fmaf(h0, w[kk * 512 + 256 + tid], ar0);
                    az1 = fmaf(h1, w[(kk + 1) * 512 + tid], az1);
                    ar1 = fmaf(h1, w[(kk + 1) * 512 + 256 + tid], ar1);
                }
                __syncthreads();
            }
        }
        float z = 1.f / (1.f + expf(-(az0 + az1)));
        float r = 1.f / (1.f + expf(-(ar0 + ar1)));
        float hold = hs[tid];
        rh[tid] = r * hold;
        __syncthreads();

        float aa0 = gx[512 + tid] + ba, aa1 = 0.f;
        // ---- a pass: 8 chunks of 32 k-rows, cols [512,768) ----
        {
            #pragma unroll
            for (int i = 0; i < 8; i++) {
                int idx = tid + i * 256;
                int row = idx >> 6, c4 = idx & 63;
                cp16(sa_u + (row * 256 + c4 * 4) * 4, wh + (size_t)row * 768 + 512 + c4 * 4);
            }
            cp_commit();
            for (int c = 0; c < 8; c++) {
                if (c < 7) {
                    int st = (c + 1) & 1;
                    int k0 = (c + 1) * 32;
                    #pragma unroll
                    for (int i = 0; i < 8; i++) {
                        int idx = tid + i * 256;
                        int row = idx >> 6, c4 = idx & 63;
                        cp16(sa_u + (st * 32 * 256 + row * 256 + c4 * 4) * 4,
                             wh + (size_t)(k0 + row) * 768 + 512 + c4 * 4);
                    }
                    cp_commit();
                    cp_wait1();
                } else {
                    cp_wait0();
                }
                __syncthreads();
                const float* w = swa + (c & 1) * 32 * 256;
                int kb = c * 32;
                #pragma unroll 4
                for (int kk = 0; kk < 32; kk += 2) {
                    aa0 = fmaf(rh[kb + kk], w[kk * 256 + tid], aa0);
                    aa1 = fmaf(rh[kb + kk + 1], w[(kk + 1) * 256 + tid], aa1);
                }
                __syncthreads();
            }
        }
        float a = tanhf(aa0 + aa1);
        float hn = (1.f - z) * hold + z * a;
        slots[((size_t)b * 11 + s) * 256 + tid] = hn;
        __syncthreads();
        hs[tid] = hn;
        __syncthreads();
    }
}

// ---------------- 7) fused MLP: slots += relu(LN(slots)@w1+b1)@w2 + b2 ----------------
__global__ void __launch_bounds__(256) k_mlp(const float* __restrict__ g, const float* __restrict__ o,
                                             const float* __restrict__ w1, const float* __restrict__ b1,
                                             const float* __restrict__ w2, const float* __restrict__ b2,
                                             float* __restrict__ slots)
{
    __shared__ float lns[256];
    __shared__ float hid[512];
    int r = blockIdx.x, tid = threadIdx.x;
    float val = slots[r * 256 + tid];
    float s_ = val, q_ = val * val;
    block_reduce2(s_, q_);
    float muv = s_ * (1.f / 256.f);
    float var = q_ * (1.f / 256.f) - muv * muv;
    float rs = rsqrtf(var + 1e-5f);
    lns[tid] = (val - muv) * rs * g[tid] + o[tid];
    __syncthreads();

    const float2* wp = (const float2*)&w1[tid * 2];
    float ax0 = 0.f, ay0 = 0.f, ax1 = 0.f, ay1 = 0.f;
    #pragma unroll 4
    for (int k = 0; k < 256; k += 2) {
        float l0 = lns[k], l1 = lns[k + 1];
        float2 w0 = wp[(size_t)k * 256];
        float2 w1v = wp[(size_t)(k + 1) * 256];
        ax0 = fmaf(l0, w0.x, ax0); ay0 = fmaf(l0, w0.y, ay0);
        ax1 = fmaf(l1, w1v.x, ax1); ay1 = fmaf(l1, w1v.y, ay1);
    }
    float2 bb = *(const float2*)&b1[tid * 2];
    hid[tid * 2]     = fmaxf(ax0 + ax1 + bb.x, 0.f);
    hid[tid * 2 + 1] = fmaxf(ay0 + ay1 + bb.y, 0.f);
    __syncthreads();

    const float* w2p = w2 + tid;
    float a0 = 0.f, a1 = 0.f, a2 = 0.f, a3 = 0.f;
    #pragma unroll 4
    for (int k = 0; k < 512; k += 4) {
        a0 = fmaf(hid[k],     w2p[(size_t)k * 256],       a0);
        a1 = fmaf(hid[k + 1], w2p[(size_t)(k + 1) * 256], a1);
        a2 = fmaf(hid[k + 2], w2p[(size_t)(k + 2) * 256], a2);
        a3 = fmaf(hid[k + 3], w2p[(size_t)(k + 3) * 256], a3);
    }
    slots[r * 256 + tid] = val + ((a0 + a1) + (a2 + a3)) + b2[tid];
}

// ---------------- host launch ----------------
extern "C" void kernel_launch(void* const* d_in, const int* in_sizes, int n_in,
                              void* d_out, int out_size)
{
    const float* inputs          = (const float*)d_in[0];
    const float* slot_noise      = (const float*)d_in[1];
    const float* ln_in_scale     = (const float*)d_in[2];
    const float* ln_in_offset    = (const float*)d_in[3];
    const float* ln_slots_scale  = (const float*)d_in[4];
    const float* ln_slots_offset = (const float*)d_in[5];
    const float* ln_mlp_scale    = (const float*)d_in[6];
    const float* ln_mlp_offset   = (const float*)d_in[7];
    const float* slots_mu        = (const float*)d_in[8];
    const float* slots_log_sigma = (const float*)d_in[9];
    const float* Wq              = (const float*)d_in[10];
    const float* Wk              = (const float*)d_in[11];
    const float* Wv              = (const float*)d_in[12];
    const float* gru_wi          = (const float*)d_in[13];
    const float* gru_wh          = (const float*)d_in[14];
    const float* gru_b           = (const float*)d_in[15];
    const float* mlp_w1          = (const float*)d_in[16];
    const float* mlp_b1          = (const float*)d_in[17];
    const float* mlp_w2          = (const float*)d_in[18];
    const float* mlp_b2          = (const float*)d_in[19];
    float* slots = (float*)d_out;

    (void)in_sizes; (void)n_in; (void)out_size;

    cudaFuncSetAttribute(k_mma_kv, cudaFuncAttributeMaxDynamicSharedMemorySize, SMEM_SZ);
    cudaFuncSetAttribute(k_gru, cudaFuncAttributeMaxDynamicSharedMemorySize, GRU_SMEM);

    k_q<<<352, 256>>>(1, slot_noise, slots_mu, slots_log_sigma,
                      ln_slots_scale, ln_slots_offset, Wq, slots);            // 0
    k_prepall<<<16384 + 512, 256>>>(inputs, ln_in_scale, ln_in_offset, Wk, Wv); // 1
    k_mma_kv<<<dim3(4, (B_ * N_) / 128), 256, SMEM_SZ>>>();                   // 2
    k_attn_upd<<<dim3(32, 16), 256>>>();                                      // 3 (profiled)
    k_gx<<<dim3(32, 3), 256>>>(gru_wi);
    k_gru<<<32, 256, GRU_SMEM>>>(gru_wh, gru_b, slots);
    k_mlp<<<352, 256>>>(ln_mlp_scale, ln_mlp_offset, mlp_w1, mlp_b1, mlp_w2, mlp_b2, slots);

    for (int it = 1; it < 3; it++) {
        k_q<<<352, 256>>>(0, slot_noise, slots_mu, slots_log_sigma,
                          ln_slots_scale, ln_slots_offset, Wq, slots);
        k_attn_upd<<<dim3(32, 16), 256>>>();
        k_gx<<<dim3(32, 3), 256>>>(gru_wi);
        k_gru<<<32, 256, GRU_SMEM>>>(gru_wh, gru_b, slots);
        k_mlp<<<352, 256>>>(ln_mlp_scale, ln_mlp_offset, mlp_w1, mlp_b1, mlp_w2, mlp_b2, slots);
    }
}